// round 9
// baseline (speedup 1.0000x reference)
#include <cuda_runtime.h>
#include <cuda_bf16.h>
#include <cstdint>
#include <math.h>

#define NB 64
#define DM 768
#define LV 576
#define LD 320
#define LA 192
#define CV 512
#define CD 256
#define CA 128

// GEMM tile config: CTA 128x128, 4 warps (2x2), warp tile 64x64 (mt=4, nt=8)
#define BM 128
#define BN 128
#define AST 24                   // conflict-free fragment loads (see R8)
#define PL  (128 * AST)
#define BUF (4 * PL)             // per stage (Ah, Al, Bh, Bl)
#define GEMM_SMEM (2 * BUF * 4)  // 98304 B

#define KPERM(jl) ((((jl) & 3) * 2) + ((jl) >> 2))

// ---------------- scratch (device globals; no runtime allocation) ----------
__device__ float g_vid[(size_t)NB * LV * DM];
__device__ float g_det[(size_t)NB * LD * DM];
__device__ float g_act[(size_t)NB * LA * DM];
__device__ uint32_t g_xvh[(size_t)NB * LV * (DM / 2)], g_xvl[(size_t)NB * LV * (DM / 2)];
__device__ uint32_t g_xdh[(size_t)NB * LD * (DM / 2)], g_xdl[(size_t)NB * LD * (DM / 2)];
__device__ uint32_t g_xah[(size_t)NB * LA * (DM / 2)], g_xal[(size_t)NB * LA * (DM / 2)];
__device__ uint32_t g_wvh[DM * (DM / 2)], g_wvl[DM * (DM / 2)];
__device__ uint32_t g_wdh[DM * (DM / 2)], g_wdl[DM * (DM / 2)];
__device__ uint32_t g_wah[DM * (DM / 2)], g_wal[DM * (DM / 2)];
__device__ uint32_t g_vh[(size_t)NB * LV * (DM / 2)], g_vl[(size_t)NB * LV * (DM / 2)];
__device__ uint32_t g_dh[(size_t)NB * LD * (DM / 2)], g_dl[(size_t)NB * LD * (DM / 2)];
__device__ uint32_t g_ah[(size_t)NB * LA * (DM / 2)], g_al[(size_t)NB * LA * (DM / 2)];
__device__ uint32_t g_vTh[(size_t)NB * DM * (LV / 2)], g_vTl[(size_t)NB * DM * (LV / 2)];
__device__ uint32_t g_dTh[(size_t)NB * DM * (LD / 2)], g_dTl[(size_t)NB * DM * (LD / 2)];
__device__ uint32_t g_aTh[(size_t)NB * DM * (LA / 2)], g_aTl[(size_t)NB * DM * (LA / 2)];
__device__ float    g_S  [(size_t)NB * LV * LD];
__device__ uint32_t g_p12h[(size_t)NB * LV * (LD / 2)], g_p12l[(size_t)NB * LV * (LD / 2)];
__device__ uint32_t g_p21h[(size_t)NB * LV * (LD / 2)], g_p21l[(size_t)NB * LV * (LD / 2)];

// ---------------- helpers ---------------------------------------------------
__device__ __forceinline__ uint32_t smem_u32(const void* p) {
    uint32_t a;
    asm("{ .reg .u64 t; cvta.to.shared.u64 t, %1; cvt.u32.u64 %0, t; }" : "=r"(a) : "l"(p));
    return a;
}

__device__ __forceinline__ void mma16816(float* d, const uint32_t* a, const uint32_t* b)
{
    asm volatile(
        "mma.sync.aligned.m16n8k16.row.col.f32.bf16.bf16.f32 "
        "{%0,%1,%2,%3}, {%4,%5,%6,%7}, {%8,%9}, {%0,%1,%2,%3};"
        : "+f"(d[0]), "+f"(d[1]), "+f"(d[2]), "+f"(d[3])
        : "r"(a[0]), "r"(a[1]), "r"(a[2]), "r"(a[3]), "r"(b[0]), "r"(b[1]));
}

__device__ __forceinline__ void pack_split(float x, float y, uint32_t& hi, uint32_t& lo)
{
    __nv_bfloat162 h = __floats2bfloat162_rn(x, y);
    float hx = __bfloat162float(__low2bfloat16(h));
    float hy = __bfloat162float(__high2bfloat16(h));
    __nv_bfloat162 l = __floats2bfloat162_rn(x - hx, y - hy);
    hi = *reinterpret_cast<uint32_t*>(&h);
    lo = *reinterpret_cast<uint32_t*>(&l);
}

// ---------------------------------------------------------------------------
// split_src: fp32 row-major [rows, Kf] -> hi/lo bf16x2 planes, pre-permuted.
// ---------------------------------------------------------------------------
__global__ __launch_bounds__(256) void split_src(
    const float* __restrict__ in, uint32_t* __restrict__ hi, uint32_t* __restrict__ lo,
    long total, int Kf)
{
    long u = (long)blockIdx.x * 256 + threadIdx.x;
    if (u >= total) return;
    const int gpr = Kf >> 4;
    long row = u / gpr;
    int grp = (int)(u - row * gpr);
    const float* p = in + row * (long)Kf + grp * 16;
    float f[16];
#pragma unroll
    for (int q = 0; q < 4; ++q) *(float4*)(f + q * 4) = *(const float4*)(p + q * 4);
    uint32_t h[8], l[8];
#pragma unroll
    for (int j = 0; j < 8; ++j) pack_split(f[2 * j], f[2 * j + 1], h[j], l[j]);
    uint32_t* dh = hi + row * (long)(Kf >> 1) + grp * 8;
    uint32_t* dl = lo + row * (long)(Kf >> 1) + grp * 8;
    *(uint4*)(dh + 0) = make_uint4(h[0], h[4], h[1], h[5]);
    *(uint4*)(dh + 4) = make_uint4(h[2], h[6], h[3], h[7]);
    *(uint4*)(dl + 0) = make_uint4(l[0], l[4], l[1], l[5]);
    *(uint4*)(dl + 4) = make_uint4(l[2], l[6], l[3], l[7]);
}

// ---------------------------------------------------------------------------
// gemm_split: NT GEMM on pre-split pre-permuted bf16 planes.
// CTA 128x128, 128 threads = 4 warps (2m x 2n), warp tile 64x64 (mt=4, nt=8).
// 3-product bf16-split accumulate; cp.async double-buffered; AST=24 layout.
// ---------------------------------------------------------------------------
__global__ __launch_bounds__(128, 2) void gemm_split(
    const uint32_t* __restrict__ Ah, const uint32_t* __restrict__ Al,
    const uint32_t* __restrict__ Bh, const uint32_t* __restrict__ Bl,
    const float* __restrict__ bias, float* __restrict__ C,
    uint32_t* __restrict__ Chi, uint32_t* __restrict__ Clo,
    int M, int N, int K, long sA, long sB, long sC, float alpha, int accum)
{
    extern __shared__ uint32_t sm[];
    const int tid = threadIdx.x;
    const int bz = blockIdx.z;
    Ah += (long)bz * sA; Al += (long)bz * sA;
    Bh += (long)bz * sB; Bl += (long)bz * sB;
    C  += (long)bz * sC;

    const int m0 = blockIdx.y * BM;
    const int n0 = blockIdx.x * BN;
    const int K2 = K >> 1;
    const int nc = K >> 5;

    const int wid = tid >> 5, lane = tid & 31;
    const int wm = wid >> 1, wn = wid & 1;
    const int g = lane >> 2, c4 = lane & 3;

    const uint32_t smem_base = smem_u32(sm);

    float acc[4][8][4];
#pragma unroll
    for (int mt = 0; mt < 4; ++mt)
#pragma unroll
        for (int nt = 0; nt < 8; ++nt)
#pragma unroll
            for (int q = 0; q < 4; ++q) acc[mt][nt][q] = 0.f;

    // staging: 4 planes x 128 rows x 4 chunks(16B) = 2048 units; 128 threads -> 16 its
    auto issue = [&](int cc, int buf) {
#pragma unroll
        for (int it = 0; it < 16; ++it) {
            const int plane = it >> 2;
            const int u = ((it & 3) << 7) + tid;
            const int row = u >> 2, ch = u & 3;
            uint32_t dst = smem_base +
                (uint32_t)((buf * BUF + plane * PL + row * AST + ch * 4) * 4);
            const uint32_t* srcb;
            bool valid;
            if (plane < 2) {
                valid = (m0 + row) < M;
                srcb = (plane == 0 ? Ah : Al) + (long)(valid ? m0 + row : 0) * K2 + cc * 16 + ch * 4;
            } else {
                valid = (n0 + row) < N;
                srcb = (plane == 2 ? Bh : Bl) + (long)(valid ? n0 + row : 0) * K2 + cc * 16 + ch * 4;
            }
            int sb = valid ? 16 : 0;
            asm volatile("cp.async.cg.shared.global [%0], [%1], 16, %2;"
                         :: "r"(dst), "l"(srcb), "r"(sb) : "memory");
        }
        asm volatile("cp.async.commit_group;" ::: "memory");
    };

    issue(0, 0);

    for (int c = 0; c < nc; ++c) {
        if (c + 1 < nc) {
            issue(c + 1, (c + 1) & 1);
            asm volatile("cp.async.wait_group 1;" ::: "memory");
        } else {
            asm volatile("cp.async.wait_group 0;" ::: "memory");
        }
        __syncthreads();

        const uint32_t* Pa_h = sm + (c & 1) * BUF;
        const uint32_t* Pa_l = Pa_h + PL;
        const uint32_t* Pb_h = Pa_h + 2 * PL;
        const uint32_t* Pb_l = Pa_h + 3 * PL;

#pragma unroll
        for (int s = 0; s < 2; ++s) {
            const int kc = s * 8 + 2 * c4;
            uint32_t af[2][4][4];   // [hi/lo][mt][4]
#pragma unroll
            for (int mt = 0; mt < 4; ++mt) {
                const int r = wm * 64 + mt * 16 + g;
                uint2 t0 = *(const uint2*)(Pa_h + r * AST + kc);
                uint2 t1 = *(const uint2*)(Pa_h + (r + 8) * AST + kc);
                af[0][mt][0] = t0.x; af[0][mt][1] = t1.x;
                af[0][mt][2] = t0.y; af[0][mt][3] = t1.y;
                t0 = *(const uint2*)(Pa_l + r * AST + kc);
                t1 = *(const uint2*)(Pa_l + (r + 8) * AST + kc);
                af[1][mt][0] = t0.x; af[1][mt][1] = t1.x;
                af[1][mt][2] = t0.y; af[1][mt][3] = t1.y;
            }
#pragma unroll
            for (int nh = 0; nh < 2; ++nh) {
                uint32_t bh[4][2], bl[4][2];
#pragma unroll
                for (int nt = 0; nt < 4; ++nt) {
                    const int rb = wn * 64 + nh * 32 + nt * 8 + g;
                    uint2 t = *(const uint2*)(Pb_h + rb * AST + kc);
                    bh[nt][0] = t.x; bh[nt][1] = t.y;
                    t = *(const uint2*)(Pb_l + rb * AST + kc);
                    bl[nt][0] = t.x; bl[nt][1] = t.y;
                }
#pragma unroll
                for (int mt = 0; mt < 4; ++mt)
#pragma unroll
                    for (int nt = 0; nt < 4; ++nt)
                        mma16816(acc[mt][nh * 4 + nt], af[0][mt], bh[nt]);
#pragma unroll
                for (int mt = 0; mt < 4; ++mt)
#pragma unroll
                    for (int nt = 0; nt < 4; ++nt)
                        mma16816(acc[mt][nh * 4 + nt], af[0][mt], bl[nt]);
#pragma unroll
                for (int mt = 0; mt < 4; ++mt)
#pragma unroll
                    for (int nt = 0; nt < 4; ++nt)
                        mma16816(acc[mt][nh * 4 + nt], af[1][mt], bh[nt]);
            }
        }
        __syncthreads();
    }

    // epilogue
#pragma unroll
    for (int mt = 0; mt < 4; ++mt)
#pragma unroll
        for (int half = 0; half < 2; ++half) {
            const int m = m0 + wm * 64 + mt * 16 + g + half * 8;
            if (m >= M) continue;
#pragma unroll
            for (int ntg = 0; ntg < 8; ++ntg) {
                const int n = n0 + wn * 64 + ntg * 8 + 2 * c4;
                if (n >= N) continue;
                float2 o;
                o.x = acc[mt][ntg][half * 2 + 0] * alpha;
                o.y = acc[mt][ntg][half * 2 + 1] * alpha;
                if (bias) { o.x += bias[n]; o.y += bias[n + 1]; }
                const long off = (long)m * N + n;
                if (accum) {
                    float2 old = *(const float2*)(C + off);
                    o.x += old.x; o.y += old.y;
                }
                *(float2*)(C + off) = o;
                if (Chi) {
                    uint32_t h, l;
                    pack_split(o.x, o.y, h, l);
                    const int jj = n >> 1, jl = jj & 7;
                    const long so = (long)m * (N >> 1) + (jj & ~7) + KPERM(jl);
                    Chi[so] = h; Clo[so] = l;
                }
            }
        }
}

// ---------------------------------------------------------------------------
// transpose_split: fp32 h[b][l][d] -> split-perm h^T planes [b][d][l/2 u32]
// ---------------------------------------------------------------------------
__global__ __launch_bounds__(256) void transpose_split(
    const float* __restrict__ in, uint32_t* __restrict__ outh,
    uint32_t* __restrict__ outl, int L)
{
    __shared__ float t[32][33];
    const int b = blockIdx.z;
    const int l0 = blockIdx.x * 32;
    const int d0 = blockIdx.y * 32;
    in += (long)b * L * DM;
    const long obase = (long)b * DM * (L >> 1);
    const int tx = threadIdx.x & 31;
    const int ty = threadIdx.x >> 5;
#pragma unroll
    for (int i = ty; i < 32; i += 8)
        t[i][tx] = in[(long)(l0 + i) * DM + d0 + tx];
    __syncthreads();
#pragma unroll
    for (int q = 0; q < 2; ++q) {
        const int u = q * 256 + threadIdx.x;
        const int dl = u >> 4, pr = u & 15;
        float v0 = t[2 * pr][dl], v1 = t[2 * pr + 1][dl];
        uint32_t h, l;
        pack_split(v0, v1, h, l);
        const int jj = (l0 >> 1) + pr, jl = jj & 7;
        const long so = obase + (long)(d0 + dl) * (L >> 1) + (jj & ~7) + KPERM(jl);
        outh[so] = h; outl[so] = l;
    }
}

// ---------------------------------------------------------------------------
// Row softmax (p12): reads fp32 S, writes split-perm P12 planes. S untouched.
// allowed = (j < c2) || (i >= c1 && i-c1 >= j-c2)
// ---------------------------------------------------------------------------
template <int L2>
__global__ __launch_bounds__(256) void softmax12(
    const float* __restrict__ S, const float* __restrict__ mk,
    uint32_t* __restrict__ Phi, uint32_t* __restrict__ Plo, int L1, int c1, int c2)
{
    constexpr int NU = L2 / 64;
    const int warp = threadIdx.x >> 5;
    const int lane = threadIdx.x & 31;
    const int b = blockIdx.y;
    const int i = blockIdx.x * 8 + warp;
    if (i >= L1) return;
    const float* row = S + ((long)b * L1 + i) * L2;
    const float* m2 = mk + (long)b * L2;

    float v[2 * NU];
    float mx = -INFINITY;
#pragma unroll
    for (int t = 0; t < NU; ++t) {
        const int jj = t * 32 + lane;
        const int j = 2 * jj;
        float2 sv = *(const float2*)(row + j);
        float2 mm = *(const float2*)(m2 + j);
        float al0 = ((j < c2) || (i >= c1 && (i - c1) >= (j - c2))) ? 1.f : 0.f;
        float al1 = ((j + 1 < c2) || (i >= c1 && (i - c1) >= (j + 1 - c2))) ? 1.f : 0.f;
        v[2 * t + 0] = sv.x + (1.f - al0 * mm.x) * -10000.f;
        v[2 * t + 1] = sv.y + (1.f - al1 * mm.y) * -10000.f;
        mx = fmaxf(mx, fmaxf(v[2 * t], v[2 * t + 1]));
    }
#pragma unroll
    for (int off = 16; off > 0; off >>= 1)
        mx = fmaxf(mx, __shfl_xor_sync(0xffffffffu, mx, off));
    float Z = 0.f;
#pragma unroll
    for (int t = 0; t < 2 * NU; ++t) { v[t] = __expf(v[t] - mx); Z += v[t]; }
#pragma unroll
    for (int off = 16; off > 0; off >>= 1)
        Z += __shfl_xor_sync(0xffffffffu, Z, off);
    const float inv = 1.f / Z;
    const long base = ((long)b * L1 + i) * (L2 >> 1);
#pragma unroll
    for (int t = 0; t < NU; ++t) {
        const int jj = t * 32 + lane, jl = jj & 7;
        uint32_t h, l;
        pack_split(v[2 * t] * inv, v[2 * t + 1] * inv, h, l);
        const long so = base + (jj & ~7) + KPERM(jl);
        Phi[so] = h; Plo[so] = l;
    }
}

// ---------------------------------------------------------------------------
// Column softmax (p21): two-pass, small static smem (high occupancy).
// P21[b,j,i] = softmax_i(S[b,i,j] + bias21), split-perm planes (rows j, k=i).
// allowed = (i < c1) || (j >= c2 && j-c2 >= i-c1)
// ---------------------------------------------------------------------------
__global__ __launch_bounds__(256) void softmax21(
    const float* __restrict__ S, const float* __restrict__ mk1,
    uint32_t* __restrict__ Phi, uint32_t* __restrict__ Plo,
    int L1, int L2, int c1, int c2)
{
    const int tx = threadIdx.x & 31;
    const int ty = threadIdx.x >> 5;
    const int b = blockIdx.y;
    const int j0 = blockIdx.x * 32;
    const int j = j0 + tx;
    const float* Sb = S + (long)b * L1 * L2;
    const float* m1 = mk1 + (long)b * L1;

    float mx = -INFINITY, Z = 0.f;
    for (int i = ty; i < L1; i += 8) {
        float allowed = ((i < c1) || (j >= c2 && (j - c2) >= (i - c1))) ? 1.f : 0.f;
        float s = Sb[(long)i * L2 + j] + (1.f - allowed * m1[i]) * -10000.f;
        if (s > mx) { Z = Z * __expf(mx - s) + 1.f; mx = s; }
        else        { Z += __expf(s - mx); }
    }
    __shared__ float smx[8][32];
    __shared__ float ssum[8][32];
    smx[ty][tx] = mx; ssum[ty][tx] = Z;
    __syncthreads();
    if (ty == 0) {
        float m = smx[0][tx], z = ssum[0][tx];
#pragma unroll
        for (int r = 1; r < 8; ++r) {
            float m2 = smx[r][tx], z2 = ssum[r][tx];
            float mm = fmaxf(m, m2);
            z = z * __expf(m - mm) + z2 * __expf(m2 - mm);
            m = mm;
        }
        smx[0][tx] = m; ssum[0][tx] = 1.f / z;
    }
    __syncthreads();
    const float rowmax = smx[0][tx];
    const float invZ = ssum[0][tx];

    __shared__ float tile[32][33];
    for (int i0 = 0; i0 < L1; i0 += 32) {
#pragma unroll
        for (int ii = ty; ii < 32; ii += 8) {
            const int i = i0 + ii;
            float allowed = ((i < c1) || (j >= c2 && (j - c2) >= (i - c1))) ? 1.f : 0.f;
            float s = Sb[(long)i * L2 + j] + (1.f - allowed * m1[i]) * -10000.f;
            tile[tx][ii] = __expf(s - rowmax) * invZ;
        }
        __syncthreads();
#pragma unroll
        for (int q = 0; q < 2; ++q) {
            const int u = q * 256 + threadIdx.x;
            const int jl2 = u >> 4, pr = u & 15;
            uint32_t h, l;
            pack_split(tile[jl2][2 * pr], tile[jl2][2 * pr + 1], h, l);
            const int jj = (i0 >> 1) + pr, jg = jj & 7;
            const long so = ((long)b * L2 + j0 + jl2) * (L1 >> 1) + (jj & ~7) + KPERM(jg);
            Phi[so] = h; Plo[so] = l;
        }
        __syncthreads();
    }
}

// ---------------------------------------------------------------------------
static inline dim3 gg(int M, int N, int batch) {
    return dim3((unsigned)((N + BN - 1) / BN), (unsigned)((M + BM - 1) / BM), (unsigned)batch);
}

extern "C" void kernel_launch(void* const* d_in, const int* in_sizes, int n_in,
                              void* d_out, int out_size)
{
    const float* vemb = (const float*)d_in[0];
    const float* mv   = (const float*)d_in[1];
    const float* demb = (const float*)d_in[2];
    const float* md   = (const float*)d_in[3];
    const float* aemb = (const float*)d_in[4];
    const float* ma   = (const float*)d_in[5];
    const float* Wv   = (const float*)d_in[6];
    const float* bv   = (const float*)d_in[7];
    const float* Wd   = (const float*)d_in[8];
    const float* bd   = (const float*)d_in[9];
    const float* Wa   = (const float*)d_in[10];
    const float* ba   = (const float*)d_in[11];

    float* out1 = (float*)d_out;
    float* out2 = out1 + (size_t)NB * LV * DM;
    float* out3 = out2 + (size_t)NB * LD * DM;

#define GA(v, s) cudaGetSymbolAddress((void**)&v, s)
    float *vid, *det, *act, *S;
    uint32_t *xvh, *xvl, *xdh, *xdl, *xah, *xal;
    uint32_t *wvh, *wvl, *wdh, *wdl, *wah, *wal;
    uint32_t *vh, *vl, *dh, *dl, *ah, *al;
    uint32_t *vTh, *vTl, *dTh, *dTl, *aTh, *aTl;
    uint32_t *p12h, *p12l, *p21h, *p21l;
    GA(vid, g_vid); GA(det, g_det); GA(act, g_act); GA(S, g_S);
    GA(xvh, g_xvh); GA(xvl, g_xvl); GA(xdh, g_xdh); GA(xdl, g_xdl);
    GA(xah, g_xah); GA(xal, g_xal);
    GA(wvh, g_wvh); GA(wvl, g_wvl); GA(wdh, g_wdh); GA(wdl, g_wdl);
    GA(wah, g_wah); GA(wal, g_wal);
    GA(vh, g_vh); GA(vl, g_vl); GA(dh, g_dh); GA(dl, g_dl);
    GA(ah, g_ah); GA(al, g_al);
    GA(vTh, g_vTh); GA(vTl, g_vTl); GA(dTh, g_dTh); GA(dTl, g_dTl);
    GA(aTh, g_aTh); GA(aTl, g_aTl);
    GA(p12h, g_p12h); GA(p12l, g_p12l); GA(p21h, g_p21h); GA(p21l, g_p21l);
#undef GA

    cudaFuncSetAttribute(gemm_split, cudaFuncAttributeMaxDynamicSharedMemorySize, GEMM_SMEM);

    const long tv = (long)NB * LV * (DM / 16), td = (long)NB * LD * (DM / 16),
               ta = (long)NB * LA * (DM / 16), tw = (long)DM * (DM / 16);

    // ---- order chosen so launch index 3 (the one ncu captures) = proj GEMM ----
    split_src<<<(unsigned)((tw + 255) / 256), 256>>>(Wv, wvh, wvl, tw, DM);     // 0
    split_src<<<(unsigned)((tv + 255) / 256), 256>>>(vemb, xvh, xvl, tv, DM);   // 1
    split_src<<<(unsigned)((tw + 255) / 256), 256>>>(Wd, wdh, wdl, tw, DM);     // 2
    // 3: captured by ncu
    gemm_split<<<gg(NB * LV, DM, 1), 128, GEMM_SMEM>>>(xvh, xvl, wvh, wvl, bv, vid,
        vh, vl, NB * LV, DM, DM, 0, 0, 0, 1.f, 0);
    split_src<<<(unsigned)((td + 255) / 256), 256>>>(demb, xdh, xdl, td, DM);   // 4
    split_src<<<(unsigned)((ta + 255) / 256), 256>>>(aemb, xah, xal, ta, DM);   // 5
    split_src<<<(unsigned)((tw + 255) / 256), 256>>>(Wa, wah, wal, tw, DM);     // 6

    gemm_split<<<gg(NB * LD, DM, 1), 128, GEMM_SMEM>>>(xdh, xdl, wdh, wdl, bd, det,
        dh, dl, NB * LD, DM, DM, 0, 0, 0, 1.f, 0);
    gemm_split<<<gg(NB * LA, DM, 1), 128, GEMM_SMEM>>>(xah, xal, wah, wal, ba, act,
        ah, al, NB * LA, DM, DM, 0, 0, 0, 1.f, 0);

    // ---- transposed split copies for PV GEMMs ----
    transpose_split<<<dim3(LV / 32, DM / 32, NB), 256>>>(vid, vTh, vTl, LV);
    transpose_split<<<dim3(LD / 32, DM / 32, NB), 256>>>(det, dTh, dTl, LD);
    transpose_split<<<dim3(LA / 32, DM / 32, NB), 256>>>(act, aTh, aTl, LA);

    // ==== pair A: vid (L1=576, c1=512) x det (L2=320, c2=256) ====
    gemm_split<<<gg(LV, LD, NB), 128, GEMM_SMEM>>>(vh, vl, dh, dl, nullptr, S,
        nullptr, nullptr, LV, LD, DM,
        (long)LV * (DM / 2), (long)LD * (DM / 2), (long)LV * LD, 0.125f, 0);
    softmax21<<<dim3(LD / 32, NB), 256>>>(S, mv, p21h, p21l, LV, LD, CV, CD);
    softmax12<LD><<<dim3(LV / 8, NB), 256>>>(S, md, p12h, p12l, LV, CV, CD);
    gemm_split<<<gg(LV, DM, NB), 128, GEMM_SMEM>>>(p12h, p12l, dTh, dTl, nullptr, out1,
        nullptr, nullptr, LV, DM, LD,
        (long)LV * (LD / 2), (long)DM * (LD / 2), (long)LV * DM, 1.f, 0);   // c_vd
    gemm_split<<<gg(LD, DM, NB), 128, GEMM_SMEM>>>(p21h, p21l, vTh, vTl, nullptr, out2,
        nullptr, nullptr, LD, DM, LV,
        (long)LD * (LV / 2), (long)DM * (LV / 2), (long)LD * DM, 1.f, 0);   // c_dv

    // ==== pair B: vid (576, 512) x act (192, 128) ====
    gemm_split<<<gg(LV, LA, NB), 128, GEMM_SMEM>>>(vh, vl, ah, al, nullptr, S,
        nullptr, nullptr, LV, LA, DM,
        (long)LV * (DM / 2), (long)LA * (DM / 2), (long)LV * LA, 0.125f, 0);
    softmax21<<<dim3(LA / 32, NB), 256>>>(S, mv, p21h, p21l, LV, LA, CV, CA);
    softmax12<LA><<<dim3(LV / 8, NB), 256>>>(S, ma, p12h, p12l, LV, CV, CA);
    gemm_split<<<gg(LV, DM, NB), 128, GEMM_SMEM>>>(p12h, p12l, aTh, aTl, nullptr, out1,
        nullptr, nullptr, LV, DM, LA,
        (long)LV * (LA / 2), (long)DM * (LA / 2), (long)LV * DM, 1.f, 1);   // += c_va
    gemm_split<<<gg(LA, DM, NB), 128, GEMM_SMEM>>>(p21h, p21l, vTh, vTl, nullptr, out3,
        nullptr, nullptr, LA, DM, LV,
        (long)LA * (LV / 2), (long)DM * (LV / 2), (long)LA * DM, 1.f, 0);   // c_av

    // ==== pair C: act (192, 128) x det (320, 256) ====
    gemm_split<<<gg(LA, LD, NB), 128, GEMM_SMEM>>>(ah, al, dh, dl, nullptr, S,
        nullptr, nullptr, LA, LD, DM,
        (long)LA * (DM / 2), (long)LD * (DM / 2), (long)LA * LD, 0.125f, 0);
    softmax21<<<dim3(LD / 32, NB), 256>>>(S, ma, p21h, p21l, LA, LD, CA, CD);
    softmax12<LD><<<dim3(LA / 8, NB), 256>>>(S, md, p12h, p12l, LA, CA, CD);
    gemm_split<<<gg(LA, DM, NB), 128, GEMM_SMEM>>>(p12h, p12l, dTh, dTl, nullptr, out3,
        nullptr, nullptr, LA, DM, LD,
        (long)LA * (LD / 2), (long)DM * (LD / 2), (long)LA * DM, 1.f, 1);   // += c_ad
    gemm_split<<<gg(LD, DM, NB), 128, GEMM_SMEM>>>(p21h, p21l, aTh, aTl, nullptr, out2,
        nullptr, nullptr, LD, DM, LA,
        (long)LD * (LA / 2), (long)DM * (LA / 2), (long)LD * DM, 1.f, 1);   // += c_da
}

// round 10
// speedup vs baseline: 1.3050x; 1.3050x over previous
#include <cuda_runtime.h>
#include <cuda_bf16.h>
#include <cstdint>
#include <math.h>

#define NB 64
#define DM 768
#define LV 576
#define LD 320
#define LA 192
#define CV 512
#define CD 256
#define CA 128

// GEMM tile config (R8 proven config)
#define BM 128
#define BN 128
#define AST 24                   // conflict-free fragment loads
#define PL  (128 * AST)
#define BUF (4 * PL)
#define GEMM_SMEM (2 * BUF * 4)  // 98304 B

#define KPERM(jl) ((((jl) & 3) * 2) + ((jl) >> 2))

// ---------------- scratch (device globals; no runtime allocation) ----------
__device__ float g_vid[(size_t)NB * LV * DM];
__device__ float g_det[(size_t)NB * LD * DM];
__device__ float g_act[(size_t)NB * LA * DM];
__device__ uint32_t g_xvh[(size_t)NB * LV * (DM / 2)], g_xvl[(size_t)NB * LV * (DM / 2)];
__device__ uint32_t g_xdh[(size_t)NB * LD * (DM / 2)], g_xdl[(size_t)NB * LD * (DM / 2)];
__device__ uint32_t g_xah[(size_t)NB * LA * (DM / 2)], g_xal[(size_t)NB * LA * (DM / 2)];
__device__ uint32_t g_wvh[DM * (DM / 2)], g_wvl[DM * (DM / 2)];
__device__ uint32_t g_wdh[DM * (DM / 2)], g_wdl[DM * (DM / 2)];
__device__ uint32_t g_wah[DM * (DM / 2)], g_wal[DM * (DM / 2)];
__device__ uint32_t g_vh[(size_t)NB * LV * (DM / 2)], g_vl[(size_t)NB * LV * (DM / 2)];
__device__ uint32_t g_dh[(size_t)NB * LD * (DM / 2)], g_dl[(size_t)NB * LD * (DM / 2)];
__device__ uint32_t g_ah[(size_t)NB * LA * (DM / 2)], g_al[(size_t)NB * LA * (DM / 2)];
__device__ uint32_t g_vTh[(size_t)NB * DM * (LV / 2)], g_vTl[(size_t)NB * DM * (LV / 2)];
__device__ uint32_t g_dTh[(size_t)NB * DM * (LD / 2)], g_dTl[(size_t)NB * DM * (LD / 2)];
__device__ uint32_t g_aTh[(size_t)NB * DM * (LA / 2)], g_aTl[(size_t)NB * DM * (LA / 2)];
// per-pair score + probability buffers (enable cross-pair overlap)
__device__ float g_SA[(size_t)NB * LV * LD];
__device__ float g_SB[(size_t)NB * LV * LA];
__device__ float g_SC[(size_t)NB * LA * LD];
__device__ uint32_t g_pA12h[(size_t)NB * LV * (LD / 2)], g_pA12l[(size_t)NB * LV * (LD / 2)];
__device__ uint32_t g_pA21h[(size_t)NB * LV * (LD / 2)], g_pA21l[(size_t)NB * LV * (LD / 2)];
__device__ uint32_t g_pB12h[(size_t)NB * LV * (LA / 2)], g_pB12l[(size_t)NB * LV * (LA / 2)];
__device__ uint32_t g_pB21h[(size_t)NB * LV * (LA / 2)], g_pB21l[(size_t)NB * LV * (LA / 2)];
__device__ uint32_t g_pC12h[(size_t)NB * LA * (LD / 2)], g_pC12l[(size_t)NB * LA * (LD / 2)];
__device__ uint32_t g_pC21h[(size_t)NB * LA * (LD / 2)], g_pC21l[(size_t)NB * LA * (LD / 2)];

// ---------------- helpers ---------------------------------------------------
__device__ __forceinline__ uint32_t smem_u32(const void* p) {
    uint32_t a;
    asm("{ .reg .u64 t; cvta.to.shared.u64 t, %1; cvt.u32.u64 %0, t; }" : "=r"(a) : "l"(p));
    return a;
}

__device__ __forceinline__ void mma16816(float* d, const uint32_t* a, const uint32_t* b)
{
    asm volatile(
        "mma.sync.aligned.m16n8k16.row.col.f32.bf16.bf16.f32 "
        "{%0,%1,%2,%3}, {%4,%5,%6,%7}, {%8,%9}, {%0,%1,%2,%3};"
        : "+f"(d[0]), "+f"(d[1]), "+f"(d[2]), "+f"(d[3])
        : "r"(a[0]), "r"(a[1]), "r"(a[2]), "r"(a[3]), "r"(b[0]), "r"(b[1]));
}

__device__ __forceinline__ void pack_split(float x, float y, uint32_t& hi, uint32_t& lo)
{
    __nv_bfloat162 h = __floats2bfloat162_rn(x, y);
    float hx = __bfloat162float(__low2bfloat16(h));
    float hy = __bfloat162float(__high2bfloat16(h));
    __nv_bfloat162 l = __floats2bfloat162_rn(x - hx, y - hy);
    hi = *reinterpret_cast<uint32_t*>(&h);
    lo = *reinterpret_cast<uint32_t*>(&l);
}

// ---------------------------------------------------------------------------
// split_src: fp32 row-major [rows, Kf] -> hi/lo bf16x2 planes, pre-permuted.
// ---------------------------------------------------------------------------
__global__ __launch_bounds__(256) void split_src(
    const float* __restrict__ in, uint32_t* __restrict__ hi, uint32_t* __restrict__ lo,
    long total, int Kf)
{
    long u = (long)blockIdx.x * 256 + threadIdx.x;
    if (u >= total) return;
    const int gpr = Kf >> 4;
    long row = u / gpr;
    int grp = (int)(u - row * gpr);
    const float* p = in + row * (long)Kf + grp * 16;
    float f[16];
#pragma unroll
    for (int q = 0; q < 4; ++q) *(float4*)(f + q * 4) = *(const float4*)(p + q * 4);
    uint32_t h[8], l[8];
#pragma unroll
    for (int j = 0; j < 8; ++j) pack_split(f[2 * j], f[2 * j + 1], h[j], l[j]);
    uint32_t* dh = hi + row * (long)(Kf >> 1) + grp * 8;
    uint32_t* dl = lo + row * (long)(Kf >> 1) + grp * 8;
    *(uint4*)(dh + 0) = make_uint4(h[0], h[4], h[1], h[5]);
    *(uint4*)(dh + 4) = make_uint4(h[2], h[6], h[3], h[7]);
    *(uint4*)(dl + 0) = make_uint4(l[0], l[4], l[1], l[5]);
    *(uint4*)(dl + 4) = make_uint4(l[2], l[6], l[3], l[7]);
}

// ---------------------------------------------------------------------------
// gemm_split: NT GEMM on pre-split pre-permuted bf16 planes. (R8 config)
// ---------------------------------------------------------------------------
__global__ __launch_bounds__(256, 2) void gemm_split(
    const uint32_t* __restrict__ Ah, const uint32_t* __restrict__ Al,
    const uint32_t* __restrict__ Bh, const uint32_t* __restrict__ Bl,
    const float* __restrict__ bias, float* __restrict__ C,
    uint32_t* __restrict__ Chi, uint32_t* __restrict__ Clo,
    int M, int N, int K, long sA, long sB, long sC, float alpha, int accum)
{
    extern __shared__ uint32_t sm[];
    const int tid = threadIdx.x;
    const int bz = blockIdx.z;
    Ah += (long)bz * sA; Al += (long)bz * sA;
    Bh += (long)bz * sB; Bl += (long)bz * sB;
    C  += (long)bz * sC;

    const int m0 = blockIdx.y * BM;
    const int n0 = blockIdx.x * BN;
    const int K2 = K >> 1;
    const int nc = K >> 5;

    const int wid = tid >> 5, lane = tid & 31;
    const int wm = wid >> 1, wn = wid & 1;
    const int g = lane >> 2, c4 = lane & 3;

    const uint32_t smem_base = smem_u32(sm);

    float acc[2][8][4];
#pragma unroll
    for (int mt = 0; mt < 2; ++mt)
#pragma unroll
        for (int nt = 0; nt < 8; ++nt)
#pragma unroll
            for (int q = 0; q < 4; ++q) acc[mt][nt][q] = 0.f;

    auto issue = [&](int cc, int buf) {
#pragma unroll
        for (int it = 0; it < 8; ++it) {
            const int plane = it >> 1;
            const int u = ((it & 1) << 8) + tid;
            const int row = u >> 2, ch = u & 3;
            uint32_t dst = smem_base +
                (uint32_t)((buf * BUF + plane * PL + row * AST + ch * 4) * 4);
            const uint32_t* srcb;
            bool valid;
            if (plane < 2) {
                valid = (m0 + row) < M;
                srcb = (plane == 0 ? Ah : Al) + (long)(valid ? m0 + row : 0) * K2 + cc * 16 + ch * 4;
            } else {
                valid = (n0 + row) < N;
                srcb = (plane == 2 ? Bh : Bl) + (long)(valid ? n0 + row : 0) * K2 + cc * 16 + ch * 4;
            }
            int sb = valid ? 16 : 0;
            asm volatile("cp.async.cg.shared.global [%0], [%1], 16, %2;"
                         :: "r"(dst), "l"(srcb), "r"(sb) : "memory");
        }
        asm volatile("cp.async.commit_group;" ::: "memory");
    };

    issue(0, 0);

    for (int c = 0; c < nc; ++c) {
        if (c + 1 < nc) {
            issue(c + 1, (c + 1) & 1);
            asm volatile("cp.async.wait_group 1;" ::: "memory");
        } else {
            asm volatile("cp.async.wait_group 0;" ::: "memory");
        }
        __syncthreads();

        const uint32_t* Pa_h = sm + (c & 1) * BUF;
        const uint32_t* Pa_l = Pa_h + PL;
        const uint32_t* Pb_h = Pa_h + 2 * PL;
        const uint32_t* Pb_l = Pa_h + 3 * PL;

#pragma unroll
        for (int s = 0; s < 2; ++s) {
            const int kc = s * 8 + 2 * c4;
            uint32_t af[2][2][4];
#pragma unroll
            for (int mt = 0; mt < 2; ++mt) {
                const int r = wm * 32 + mt * 16 + g;
                uint2 t0 = *(const uint2*)(Pa_h + r * AST + kc);
                uint2 t1 = *(const uint2*)(Pa_h + (r + 8) * AST + kc);
                af[0][mt][0] = t0.x; af[0][mt][1] = t1.x;
                af[0][mt][2] = t0.y; af[0][mt][3] = t1.y;
                t0 = *(const uint2*)(Pa_l + r * AST + kc);
                t1 = *(const uint2*)(Pa_l + (r + 8) * AST + kc);
                af[1][mt][0] = t0.x; af[1][mt][1] = t1.x;
                af[1][mt][2] = t0.y; af[1][mt][3] = t1.y;
            }
#pragma unroll
            for (int nh = 0; nh < 2; ++nh) {
                uint32_t bh[4][2], bl[4][2];
#pragma unroll
                for (int nt = 0; nt < 4; ++nt) {
                    const int rb = wn * 64 + nh * 32 + nt * 8 + g;
                    uint2 t = *(const uint2*)(Pb_h + rb * AST + kc);
                    bh[nt][0] = t.x; bh[nt][1] = t.y;
                    t = *(const uint2*)(Pb_l + rb * AST + kc);
                    bl[nt][0] = t.x; bl[nt][1] = t.y;
                }
#pragma unroll
                for (int mt = 0; mt < 2; ++mt)
#pragma unroll
                    for (int nt = 0; nt < 4; ++nt)
                        mma16816(acc[mt][nh * 4 + nt], af[0][mt], bh[nt]);
#pragma unroll
                for (int mt = 0; mt < 2; ++mt)
#pragma unroll
                    for (int nt = 0; nt < 4; ++nt)
                        mma16816(acc[mt][nh * 4 + nt], af[0][mt], bl[nt]);
#pragma unroll
                for (int mt = 0; mt < 2; ++mt)
#pragma unroll
                    for (int nt = 0; nt < 4; ++nt)
                        mma16816(acc[mt][nh * 4 + nt], af[1][mt], bh[nt]);
            }
        }
        __syncthreads();
    }

    // epilogue
#pragma unroll
    for (int mt = 0; mt < 2; ++mt)
#pragma unroll
        for (int half = 0; half < 2; ++half) {
            const int m = m0 + wm * 32 + mt * 16 + g + half * 8;
            if (m >= M) continue;
#pragma unroll
            for (int ntg = 0; ntg < 8; ++ntg) {
                const int n = n0 + wn * 64 + ntg * 8 + 2 * c4;
                if (n >= N) continue;
                float2 o;
                o.x = acc[mt][ntg][half * 2 + 0] * alpha;
                o.y = acc[mt][ntg][half * 2 + 1] * alpha;
                if (bias) { o.x += bias[n]; o.y += bias[n + 1]; }
                const long off = (long)m * N + n;
                if (accum) {
                    float2 old = *(const float2*)(C + off);
                    o.x += old.x; o.y += old.y;
                }
                *(float2*)(C + off) = o;
                if (Chi) {
                    uint32_t h, l;
                    pack_split(o.x, o.y, h, l);
                    const int jj = n >> 1, jl = jj & 7;
                    const long so = (long)m * (N >> 1) + (jj & ~7) + KPERM(jl);
                    Chi[so] = h; Clo[so] = l;
                }
            }
        }
}

// ---------------------------------------------------------------------------
// transpose_split: fp32 h[b][l][d] -> split-perm h^T planes [b][d][l/2 u32]
// ---------------------------------------------------------------------------
__global__ __launch_bounds__(256) void transpose_split(
    const float* __restrict__ in, uint32_t* __restrict__ outh,
    uint32_t* __restrict__ outl, int L)
{
    __shared__ float t[32][33];
    const int b = blockIdx.z;
    const int l0 = blockIdx.x * 32;
    const int d0 = blockIdx.y * 32;
    in += (long)b * L * DM;
    const long obase = (long)b * DM * (L >> 1);
    const int tx = threadIdx.x & 31;
    const int ty = threadIdx.x >> 5;
#pragma unroll
    for (int i = ty; i < 32; i += 8)
        t[i][tx] = in[(long)(l0 + i) * DM + d0 + tx];
    __syncthreads();
#pragma unroll
    for (int q = 0; q < 2; ++q) {
        const int u = q * 256 + threadIdx.x;
        const int dl = u >> 4, pr = u & 15;
        float v0 = t[2 * pr][dl], v1 = t[2 * pr + 1][dl];
        uint32_t h, l;
        pack_split(v0, v1, h, l);
        const int jj = (l0 >> 1) + pr, jl = jj & 7;
        const long so = obase + (long)(d0 + dl) * (L >> 1) + (jj & ~7) + KPERM(jl);
        outh[so] = h; outl[so] = l;
    }
}

// ---------------------------------------------------------------------------
// Row softmax (p12): reads fp32 S, writes split-perm P12 planes. S untouched.
// ---------------------------------------------------------------------------
template <int L2>
__global__ __launch_bounds__(256) void softmax12(
    const float* __restrict__ S, const float* __restrict__ mk,
    uint32_t* __restrict__ Phi, uint32_t* __restrict__ Plo, int L1, int c1, int c2)
{
    constexpr int NU = L2 / 64;
    const int warp = threadIdx.x >> 5;
    const int lane = threadIdx.x & 31;
    const int b = blockIdx.y;
    const int i = blockIdx.x * 8 + warp;
    if (i >= L1) return;
    const float* row = S + ((long)b * L1 + i) * L2;
    const float* m2 = mk + (long)b * L2;

    float v[2 * NU];
    float mx = -INFINITY;
#pragma unroll
    for (int t = 0; t < NU; ++t) {
        const int jj = t * 32 + lane;
        const int j = 2 * jj;
        float2 sv = *(const float2*)(row + j);
        float2 mm = *(const float2*)(m2 + j);
        float al0 = ((j < c2) || (i >= c1 && (i - c1) >= (j - c2))) ? 1.f : 0.f;
        float al1 = ((j + 1 < c2) || (i >= c1 && (i - c1) >= (j + 1 - c2))) ? 1.f : 0.f;
        v[2 * t + 0] = sv.x + (1.f - al0 * mm.x) * -10000.f;
        v[2 * t + 1] = sv.y + (1.f - al1 * mm.y) * -10000.f;
        mx = fmaxf(mx, fmaxf(v[2 * t], v[2 * t + 1]));
    }
#pragma unroll
    for (int off = 16; off > 0; off >>= 1)
        mx = fmaxf(mx, __shfl_xor_sync(0xffffffffu, mx, off));
    float Z = 0.f;
#pragma unroll
    for (int t = 0; t < 2 * NU; ++t) { v[t] = __expf(v[t] - mx); Z += v[t]; }
#pragma unroll
    for (int off = 16; off > 0; off >>= 1)
        Z += __shfl_xor_sync(0xffffffffu, Z, off);
    const float inv = 1.f / Z;
    const long base = ((long)b * L1 + i) * (L2 >> 1);
#pragma unroll
    for (int t = 0; t < NU; ++t) {
        const int jj = t * 32 + lane, jl = jj & 7;
        uint32_t h, l;
        pack_split(v[2 * t] * inv, v[2 * t + 1] * inv, h, l);
        const long so = base + (jj & ~7) + KPERM(jl);
        Phi[so] = h; Plo[so] = l;
    }
}

// ---------------------------------------------------------------------------
// Column softmax (p21): two-pass, small static smem (high occupancy).
// ---------------------------------------------------------------------------
__global__ __launch_bounds__(256) void softmax21(
    const float* __restrict__ S, const float* __restrict__ mk1,
    uint32_t* __restrict__ Phi, uint32_t* __restrict__ Plo,
    int L1, int L2, int c1, int c2)
{
    const int tx = threadIdx.x & 31;
    const int ty = threadIdx.x >> 5;
    const int b = blockIdx.y;
    const int j0 = blockIdx.x * 32;
    const int j = j0 + tx;
    const float* Sb = S + (long)b * L1 * L2;
    const float* m1 = mk1 + (long)b * L1;

    float mx = -INFINITY, Z = 0.f;
    for (int i = ty; i < L1; i += 8) {
        float allowed = ((i < c1) || (j >= c2 && (j - c2) >= (i - c1))) ? 1.f : 0.f;
        float s = Sb[(long)i * L2 + j] + (1.f - allowed * m1[i]) * -10000.f;
        if (s > mx) { Z = Z * __expf(mx - s) + 1.f; mx = s; }
        else        { Z += __expf(s - mx); }
    }
    __shared__ float smx[8][32];
    __shared__ float ssum[8][32];
    smx[ty][tx] = mx; ssum[ty][tx] = Z;
    __syncthreads();
    if (ty == 0) {
        float m = smx[0][tx], z = ssum[0][tx];
#pragma unroll
        for (int r = 1; r < 8; ++r) {
            float m2 = smx[r][tx], z2 = ssum[r][tx];
            float mm = fmaxf(m, m2);
            z = z * __expf(m - mm) + z2 * __expf(m2 - mm);
            m = mm;
        }
        smx[0][tx] = m; ssum[0][tx] = 1.f / z;
    }
    __syncthreads();
    const float rowmax = smx[0][tx];
    const float invZ = ssum[0][tx];

    __shared__ float tile[32][33];
    for (int i0 = 0; i0 < L1; i0 += 32) {
#pragma unroll
        for (int ii = ty; ii < 32; ii += 8) {
            const int i = i0 + ii;
            float allowed = ((i < c1) || (j >= c2 && (j - c2) >= (i - c1))) ? 1.f : 0.f;
            float s = Sb[(long)i * L2 + j] + (1.f - allowed * m1[i]) * -10000.f;
            tile[tx][ii] = __expf(s - rowmax) * invZ;
        }
        __syncthreads();
#pragma unroll
        for (int q = 0; q < 2; ++q) {
            const int u = q * 256 + threadIdx.x;
            const int jl2 = u >> 4, pr = u & 15;
            uint32_t h, l;
            pack_split(tile[jl2][2 * pr], tile[jl2][2 * pr + 1], h, l);
            const int jj = (i0 >> 1) + pr, jg = jj & 7;
            const long so = ((long)b * L2 + j0 + jl2) * (L1 >> 1) + (jj & ~7) + KPERM(jg);
            Phi[so] = h; Plo[so] = l;
        }
        __syncthreads();
    }
}

// ---------------------------------------------------------------------------
static inline dim3 gg(int M, int N, int batch) {
    return dim3((unsigned)((N + BN - 1) / BN), (unsigned)((M + BM - 1) / BM), (unsigned)batch);
}

extern "C" void kernel_launch(void* const* d_in, const int* in_sizes, int n_in,
                              void* d_out, int out_size)
{
    const float* vemb = (const float*)d_in[0];
    const float* mv   = (const float*)d_in[1];
    const float* demb = (const float*)d_in[2];
    const float* md   = (const float*)d_in[3];
    const float* aemb = (const float*)d_in[4];
    const float* ma   = (const float*)d_in[5];
    const float* Wv   = (const float*)d_in[6];
    const float* bv   = (const float*)d_in[7];
    const float* Wd   = (const float*)d_in[8];
    const float* bd   = (const float*)d_in[9];
    const float* Wa   = (const float*)d_in[10];
    const float* ba   = (const float*)d_in[11];

    float* out1 = (float*)d_out;
    float* out2 = out1 + (size_t)NB * LV * DM;
    float* out3 = out2 + (size_t)NB * LD * DM;

#define GA(v, s) cudaGetSymbolAddress((void**)&v, s)
    float *vid, *det, *act, *SA, *SB, *SC;
    uint32_t *xvh, *xvl, *xdh, *xdl, *xah, *xal;
    uint32_t *wvh, *wvl, *wdh, *wdl, *wah, *wal;
    uint32_t *vh, *vl, *dh, *dl, *ah, *al;
    uint32_t *vTh, *vTl, *dTh, *dTl, *aTh, *aTl;
    uint32_t *pA12h, *pA12l, *pA21h, *pA21l;
    uint32_t *pB12h, *pB12l, *pB21h, *pB21l;
    uint32_t *pC12h, *pC12l, *pC21h, *pC21l;
    GA(vid, g_vid); GA(det, g_det); GA(act, g_act);
    GA(SA, g_SA); GA(SB, g_SB); GA(SC, g_SC);
    GA(xvh, g_xvh); GA(xvl, g_xvl); GA(xdh, g_xdh); GA(xdl, g_xdl);
    GA(xah, g_xah); GA(xal, g_xal);
    GA(wvh, g_wvh); GA(wvl, g_wvl); GA(wdh, g_wdh); GA(wdl, g_wdl);
    GA(wah, g_wah); GA(wal, g_wal);
    GA(vh, g_vh); GA(vl, g_vl); GA(dh, g_dh); GA(dl, g_dl);
    GA(ah, g_ah); GA(al, g_al);
    GA(vTh, g_vTh); GA(vTl, g_vTl); GA(dTh, g_dTh); GA(dTl, g_dTl);
    GA(aTh, g_aTh); GA(aTl, g_aTl);
    GA(pA12h, g_pA12h); GA(pA12l, g_pA12l); GA(pA21h, g_pA21h); GA(pA21l, g_pA21l);
    GA(pB12h, g_pB12h); GA(pB12l, g_pB12l); GA(pB21h, g_pB21h); GA(pB21l, g_pB21l);
    GA(pC12h, g_pC12h); GA(pC12l, g_pC12l); GA(pC21h, g_pC21h); GA(pC21l, g_pC21l);
#undef GA

    cudaFuncSetAttribute(gemm_split, cudaFuncAttributeMaxDynamicSharedMemorySize, GEMM_SMEM);

    // ---- one-time host resources (no device allocation) ----
    static cudaStream_t s1 = nullptr, s2 = nullptr;
    static cudaEvent_t evFork, evD, evA2, evJoin, evO1, evO2, evO3, evB, evC;
    if (!s1) {
        cudaStreamCreateWithFlags(&s1, cudaStreamNonBlocking);
        cudaStreamCreateWithFlags(&s2, cudaStreamNonBlocking);
        cudaEventCreateWithFlags(&evFork, cudaEventDisableTiming);
        cudaEventCreateWithFlags(&evD,    cudaEventDisableTiming);
        cudaEventCreateWithFlags(&evA2,   cudaEventDisableTiming);
        cudaEventCreateWithFlags(&evJoin, cudaEventDisableTiming);
        cudaEventCreateWithFlags(&evO1,   cudaEventDisableTiming);
        cudaEventCreateWithFlags(&evO2,   cudaEventDisableTiming);
        cudaEventCreateWithFlags(&evO3,   cudaEventDisableTiming);
        cudaEventCreateWithFlags(&evB,    cudaEventDisableTiming);
        cudaEventCreateWithFlags(&evC,    cudaEventDisableTiming);
    }

    const long tv = (long)NB * LV * (DM / 16), td = (long)NB * LD * (DM / 16),
               ta = (long)NB * LA * (DM / 16), tw = (long)DM * (DM / 16);

    // ===== phase 0: fork the three projection chains =====
    cudaEventRecord(evFork, 0);
    cudaStreamWaitEvent(s1, evFork, 0);
    cudaStreamWaitEvent(s2, evFork, 0);

    // default stream: vid chain
    split_src<<<(unsigned)((tw + 255) / 256), 256>>>(Wv, wvh, wvl, tw, DM);
    split_src<<<(unsigned)((tv + 255) / 256), 256>>>(vemb, xvh, xvl, tv, DM);
    gemm_split<<<gg(NB * LV, DM, 1), 256, GEMM_SMEM>>>(xvh, xvl, wvh, wvl, bv, vid,
        vh, vl, NB * LV, DM, DM, 0, 0, 0, 1.f, 0);
    transpose_split<<<dim3(LV / 32, DM / 32, NB), 256>>>(vid, vTh, vTl, LV);

    // s1: det chain
    split_src<<<(unsigned)((tw + 255) / 256), 256, 0, s1>>>(Wd, wdh, wdl, tw, DM);
    split_src<<<(unsigned)((td + 255) / 256), 256, 0, s1>>>(demb, xdh, xdl, td, DM);
    gemm_split<<<gg(NB * LD, DM, 1), 256, GEMM_SMEM, s1>>>(xdh, xdl, wdh, wdl, bd, det,
        dh, dl, NB * LD, DM, DM, 0, 0, 0, 1.f, 0);
    transpose_split<<<dim3(LD / 32, DM / 32, NB), 256, 0, s1>>>(det, dTh, dTl, LD);
    cudaEventRecord(evD, s1);

    // s2: act chain
    split_src<<<(unsigned)((tw + 255) / 256), 256, 0, s2>>>(Wa, wah, wal, tw, DM);
    split_src<<<(unsigned)((ta + 255) / 256), 256, 0, s2>>>(aemb, xah, xal, ta, DM);
    gemm_split<<<gg(NB * LA, DM, 1), 256, GEMM_SMEM, s2>>>(xah, xal, wah, wal, ba, act,
        ah, al, NB * LA, DM, DM, 0, 0, 0, 1.f, 0);
    transpose_split<<<dim3(LA / 32, DM / 32, NB), 256, 0, s2>>>(act, aTh, aTl, LA);
    cudaEventRecord(evA2, s2);

    // join: default has vid; wait for det + act, then re-fork for pairs
    cudaStreamWaitEvent(0, evD, 0);
    cudaStreamWaitEvent(0, evA2, 0);
    cudaEventRecord(evJoin, 0);
    cudaStreamWaitEvent(s1, evJoin, 0);
    cudaStreamWaitEvent(s2, evJoin, 0);

    // ===== pair A (default): vid x det (L1=576,c1=512; L2=320,c2=256) =====
    gemm_split<<<gg(LV, LD, NB), 256, GEMM_SMEM>>>(vh, vl, dh, dl, nullptr, SA,
        nullptr, nullptr, LV, LD, DM,
        (long)LV * (DM / 2), (long)LD * (DM / 2), (long)LV * LD, 0.125f, 0);
    softmax21<<<dim3(LD / 32, NB), 256>>>(SA, mv, pA21h, pA21l, LV, LD, CV, CD);
    softmax12<LD><<<dim3(LV / 8, NB), 256>>>(SA, md, pA12h, pA12l, LV, CV, CD);
    gemm_split<<<gg(LV, DM, NB), 256, GEMM_SMEM>>>(pA12h, pA12l, dTh, dTl, nullptr, out1,
        nullptr, nullptr, LV, DM, LD,
        (long)LV * (LD / 2), (long)DM * (LD / 2), (long)LV * DM, 1.f, 0);   // c_vd
    cudaEventRecord(evO1, 0);
    gemm_split<<<gg(LD, DM, NB), 256, GEMM_SMEM>>>(pA21h, pA21l, vTh, vTl, nullptr, out2,
        nullptr, nullptr, LD, DM, LV,
        (long)LD * (LV / 2), (long)DM * (LV / 2), (long)LD * DM, 1.f, 0);   // c_dv
    cudaEventRecord(evO2, 0);

    // ===== pair B (s1): vid x act (L1=576,c1=512; L2=192,c2=128) =====
    gemm_split<<<gg(LV, LA, NB), 256, GEMM_SMEM, s1>>>(vh, vl, ah, al, nullptr, SB,
        nullptr, nullptr, LV, LA, DM,
        (long)LV * (DM / 2), (long)LA * (DM / 2), (long)LV * LA, 0.125f, 0);
    softmax21<<<dim3(LA / 32, NB), 256, 0, s1>>>(SB, mv, pB21h, pB21l, LV, LA, CV, CA);
    softmax12<LA><<<dim3(LV / 8, NB), 256, 0, s1>>>(SB, ma, pB12h, pB12l, LV, CV, CA);
    gemm_split<<<gg(LA, DM, NB), 256, GEMM_SMEM, s1>>>(pB21h, pB21l, vTh, vTl, nullptr, out3,
        nullptr, nullptr, LA, DM, LV,
        (long)LA * (LV / 2), (long)DM * (LV / 2), (long)LA * DM, 1.f, 0);   // c_av
    cudaEventRecord(evO3, s1);
    cudaStreamWaitEvent(s1, evO1, 0);
    gemm_split<<<gg(LV, DM, NB), 256, GEMM_SMEM, s1>>>(pB12h, pB12l, aTh, aTl, nullptr, out1,
        nullptr, nullptr, LV, DM, LA,
        (long)LV * (LA / 2), (long)DM * (LA / 2), (long)LV * DM, 1.f, 1);   // += c_va
    cudaEventRecord(evB, s1);

    // ===== pair C (s2): act x det (L1=192,c1=128; L2=320,c2=256) =====
    gemm_split<<<gg(LA, LD, NB), 256, GEMM_SMEM, s2>>>(ah, al, dh, dl, nullptr, SC,
        nullptr, nullptr, LA, LD, DM,
        (long)LA * (DM / 2), (long)LD * (DM / 2), (long)LA * LD, 0.125f, 0);
    softmax21<<<dim3(LD / 32, NB), 256, 0, s2>>>(SC, ma, pC21h, pC21l, LA, LD, CA, CD);
    softmax12<LD><<<dim3(LA / 8, NB), 256, 0, s2>>>(SC, md, pC12h, pC12l, LA, CA, CD);
    cudaStreamWaitEvent(s2, evO2, 0);
    gemm_split<<<gg(LD, DM, NB), 256, GEMM_SMEM, s2>>>(pC21h, pC21l, aTh, aTl, nullptr, out2,
        nullptr, nullptr, LD, DM, LA,
        (long)LD * (LA / 2), (long)DM * (LA / 2), (long)LD * DM, 1.f, 1);   // += c_da
    cudaStreamWaitEvent(s2, evO3, 0);
    gemm_split<<<gg(LA, DM, NB), 256, GEMM_SMEM, s2>>>(pC12h, pC12l, dTh, dTl, nullptr, out3,
        nullptr, nullptr, LA, DM, LD,
        (long)LA * (LD / 2), (long)DM * (LD / 2), (long)LA * DM, 1.f, 1);   // += c_ad
    cudaEventRecord(evC, s2);

    // final join onto default stream
    cudaStreamWaitEvent(0, evB, 0);
    cudaStreamWaitEvent(0, evC, 0);
}

// round 11
// speedup vs baseline: 1.3593x; 1.0417x over previous
#include <cuda_runtime.h>
#include <cuda_bf16.h>
#include <cstdint>
#include <math.h>

#define NB 64
#define DM 768
#define LV 576
#define LD 320
#define LA 192
#define CV 512
#define CD 256
#define CA 128

// GEMM tile config (R8 proven config)
#define BM 128
#define BN 128
#define AST 24                   // conflict-free fragment loads
#define PL  (128 * AST)
#define BUF (4 * PL)
#define GEMM_SMEM (2 * BUF * 4)  // 98304 B

#define KPERM(jl) ((((jl) & 3) * 2) + ((jl) >> 2))

// combined-K layout (u32 units per row)
#define K1 512                   // out1: [p12A(320) | p12B(192)]
#define K2C 768                  // out2: [p21A(576) | p21C(192)]
#define K3 896                   // out3: [p21B(576) | p12C(320)]
#define S1 (K1 / 2)              // 256
#define S2 (K2C / 2)             // 384
#define S3 (K3 / 2)              // 448
#define OFF_B1_ACT 160           // act segment offset in B1/P1 (u32)
#define OFF_288 288              // vid-length offset (576/2)

// ---------------- scratch (device globals; no runtime allocation) ----------
__device__ float g_vid[(size_t)NB * LV * DM];
__device__ float g_det[(size_t)NB * LD * DM];
__device__ float g_act[(size_t)NB * LA * DM];
__device__ uint32_t g_xvh[(size_t)NB * LV * (DM / 2)], g_xvl[(size_t)NB * LV * (DM / 2)];
__device__ uint32_t g_xdh[(size_t)NB * LD * (DM / 2)], g_xdl[(size_t)NB * LD * (DM / 2)];
__device__ uint32_t g_xah[(size_t)NB * LA * (DM / 2)], g_xal[(size_t)NB * LA * (DM / 2)];
__device__ uint32_t g_wvh[DM * (DM / 2)], g_wvl[DM * (DM / 2)];
__device__ uint32_t g_wdh[DM * (DM / 2)], g_wdl[DM * (DM / 2)];
__device__ uint32_t g_wah[DM * (DM / 2)], g_wal[DM * (DM / 2)];
__device__ uint32_t g_vh[(size_t)NB * LV * (DM / 2)], g_vl[(size_t)NB * LV * (DM / 2)];
__device__ uint32_t g_dh[(size_t)NB * LD * (DM / 2)], g_dl[(size_t)NB * LD * (DM / 2)];
__device__ uint32_t g_ah[(size_t)NB * LA * (DM / 2)], g_al[(size_t)NB * LA * (DM / 2)];
// combined transposed-B buffers: rows d (768), packed k segments
__device__ uint32_t g_B1h[(size_t)NB * DM * S1], g_B1l[(size_t)NB * DM * S1];
__device__ uint32_t g_B2h[(size_t)NB * DM * S2], g_B2l[(size_t)NB * DM * S2];
__device__ uint32_t g_B3h[(size_t)NB * DM * S3], g_B3l[(size_t)NB * DM * S3];
// scores
__device__ float g_SA[(size_t)NB * LV * LD];
__device__ float g_SB[(size_t)NB * LV * LA];
__device__ float g_SC[(size_t)NB * LA * LD];
// combined probability buffers
__device__ uint32_t g_P1h[(size_t)NB * LV * S1], g_P1l[(size_t)NB * LV * S1];
__device__ uint32_t g_P2h[(size_t)NB * LD * S2], g_P2l[(size_t)NB * LD * S2];
__device__ uint32_t g_P3h[(size_t)NB * LA * S3], g_P3l[(size_t)NB * LA * S3];

// ---------------- helpers ---------------------------------------------------
__device__ __forceinline__ uint32_t smem_u32(const void* p) {
    uint32_t a;
    asm("{ .reg .u64 t; cvta.to.shared.u64 t, %1; cvt.u32.u64 %0, t; }" : "=r"(a) : "l"(p));
    return a;
}

__device__ __forceinline__ void mma16816(float* d, const uint32_t* a, const uint32_t* b)
{
    asm volatile(
        "mma.sync.aligned.m16n8k16.row.col.f32.bf16.bf16.f32 "
        "{%0,%1,%2,%3}, {%4,%5,%6,%7}, {%8,%9}, {%0,%1,%2,%3};"
        : "+f"(d[0]), "+f"(d[1]), "+f"(d[2]), "+f"(d[3])
        : "r"(a[0]), "r"(a[1]), "r"(a[2]), "r"(a[3]), "r"(b[0]), "r"(b[1]));
}

__device__ __forceinline__ void pack_split(float x, float y, uint32_t& hi, uint32_t& lo)
{
    __nv_bfloat162 h = __floats2bfloat162_rn(x, y);
    float hx = __bfloat162float(__low2bfloat16(h));
    float hy = __bfloat162float(__high2bfloat16(h));
    __nv_bfloat162 l = __floats2bfloat162_rn(x - hx, y - hy);
    hi = *reinterpret_cast<uint32_t*>(&h);
    lo = *reinterpret_cast<uint32_t*>(&l);
}

// ---------------------------------------------------------------------------
// split_src: fp32 row-major [rows, Kf] -> hi/lo bf16x2 planes, pre-permuted.
// ---------------------------------------------------------------------------
__global__ __launch_bounds__(256) void split_src(
    const float* __restrict__ in, uint32_t* __restrict__ hi, uint32_t* __restrict__ lo,
    long total, int Kf)
{
    long u = (long)blockIdx.x * 256 + threadIdx.x;
    if (u >= total) return;
    const int gpr = Kf >> 4;
    long row = u / gpr;
    int grp = (int)(u - row * gpr);
    const float* p = in + row * (long)Kf + grp * 16;
    float f[16];
#pragma unroll
    for (int q = 0; q < 4; ++q) *(float4*)(f + q * 4) = *(const float4*)(p + q * 4);
    uint32_t h[8], l[8];
#pragma unroll
    for (int j = 0; j < 8; ++j) pack_split(f[2 * j], f[2 * j + 1], h[j], l[j]);
    uint32_t* dh = hi + row * (long)(Kf >> 1) + grp * 8;
    uint32_t* dl = lo + row * (long)(Kf >> 1) + grp * 8;
    *(uint4*)(dh + 0) = make_uint4(h[0], h[4], h[1], h[5]);
    *(uint4*)(dh + 4) = make_uint4(h[2], h[6], h[3], h[7]);
    *(uint4*)(dl + 0) = make_uint4(l[0], l[4], l[1], l[5]);
    *(uint4*)(dl + 4) = make_uint4(l[2], l[6], l[3], l[7]);
}

// ---------------------------------------------------------------------------
// gemm_split: NT GEMM on pre-split pre-permuted bf16 planes. (R8 config)
// A rows stride K/2 u32, B rows stride K/2 u32 (packed).
// ---------------------------------------------------------------------------
__global__ __launch_bounds__(256, 2) void gemm_split(
    const uint32_t* __restrict__ Ah, const uint32_t* __restrict__ Al,
    const uint32_t* __restrict__ Bh, const uint32_t* __restrict__ Bl,
    const float* __restrict__ bias, float* __restrict__ C,
    uint32_t* __restrict__ Chi, uint32_t* __restrict__ Clo,
    int M, int N, int K, long sA, long sB, long sC, float alpha, int accum)
{
    extern __shared__ uint32_t sm[];
    const int tid = threadIdx.x;
    const int bz = blockIdx.z;
    Ah += (long)bz * sA; Al += (long)bz * sA;
    Bh += (long)bz * sB; Bl += (long)bz * sB;
    C  += (long)bz * sC;

    const int m0 = blockIdx.y * BM;
    const int n0 = blockIdx.x * BN;
    const int K2 = K >> 1;
    const int nc = K >> 5;

    const int wid = tid >> 5, lane = tid & 31;
    const int wm = wid >> 1, wn = wid & 1;
    const int g = lane >> 2, c4 = lane & 3;

    const uint32_t smem_base = smem_u32(sm);

    float acc[2][8][4];
#pragma unroll
    for (int mt = 0; mt < 2; ++mt)
#pragma unroll
        for (int nt = 0; nt < 8; ++nt)
#pragma unroll
            for (int q = 0; q < 4; ++q) acc[mt][nt][q] = 0.f;

    auto issue = [&](int cc, int buf) {
#pragma unroll
        for (int it = 0; it < 8; ++it) {
            const int plane = it >> 1;
            const int u = ((it & 1) << 8) + tid;
            const int row = u >> 2, ch = u & 3;
            uint32_t dst = smem_base +
                (uint32_t)((buf * BUF + plane * PL + row * AST + ch * 4) * 4);
            const uint32_t* srcb;
            bool valid;
            if (plane < 2) {
                valid = (m0 + row) < M;
                srcb = (plane == 0 ? Ah : Al) + (long)(valid ? m0 + row : 0) * K2 + cc * 16 + ch * 4;
            } else {
                valid = (n0 + row) < N;
                srcb = (plane == 2 ? Bh : Bl) + (long)(valid ? n0 + row : 0) * K2 + cc * 16 + ch * 4;
            }
            int sb = valid ? 16 : 0;
            asm volatile("cp.async.cg.shared.global [%0], [%1], 16, %2;"
                         :: "r"(dst), "l"(srcb), "r"(sb) : "memory");
        }
        asm volatile("cp.async.commit_group;" ::: "memory");
    };

    issue(0, 0);

    for (int c = 0; c < nc; ++c) {
        if (c + 1 < nc) {
            issue(c + 1, (c + 1) & 1);
            asm volatile("cp.async.wait_group 1;" ::: "memory");
        } else {
            asm volatile("cp.async.wait_group 0;" ::: "memory");
        }
        __syncthreads();

        const uint32_t* Pa_h = sm + (c & 1) * BUF;
        const uint32_t* Pa_l = Pa_h + PL;
        const uint32_t* Pb_h = Pa_h + 2 * PL;
        const uint32_t* Pb_l = Pa_h + 3 * PL;

#pragma unroll
        for (int s = 0; s < 2; ++s) {
            const int kc = s * 8 + 2 * c4;
            uint32_t af[2][2][4];
#pragma unroll
            for (int mt = 0; mt < 2; ++mt) {
                const int r = wm * 32 + mt * 16 + g;
                uint2 t0 = *(const uint2*)(Pa_h + r * AST + kc);
                uint2 t1 = *(const uint2*)(Pa_h + (r + 8) * AST + kc);
                af[0][mt][0] = t0.x; af[0][mt][1] = t1.x;
                af[0][mt][2] = t0.y; af[0][mt][3] = t1.y;
                t0 = *(const uint2*)(Pa_l + r * AST + kc);
                t1 = *(const uint2*)(Pa_l + (r + 8) * AST + kc);
                af[1][mt][0] = t0.x; af[1][mt][1] = t1.x;
                af[1][mt][2] = t0.y; af[1][mt][3] = t1.y;
            }
#pragma unroll
            for (int nh = 0; nh < 2; ++nh) {
                uint32_t bh[4][2], bl[4][2];
#pragma unroll
                for (int nt = 0; nt < 4; ++nt) {
                    const int rb = wn * 64 + nh * 32 + nt * 8 + g;
                    uint2 t = *(const uint2*)(Pb_h + rb * AST + kc);
                    bh[nt][0] = t.x; bh[nt][1] = t.y;
                    t = *(const uint2*)(Pb_l + rb * AST + kc);
                    bl[nt][0] = t.x; bl[nt][1] = t.y;
                }
#pragma unroll
                for (int mt = 0; mt < 2; ++mt)
#pragma unroll
                    for (int nt = 0; nt < 4; ++nt)
                        mma16816(acc[mt][nh * 4 + nt], af[0][mt], bh[nt]);
#pragma unroll
                for (int mt = 0; mt < 2; ++mt)
#pragma unroll
                    for (int nt = 0; nt < 4; ++nt)
                        mma16816(acc[mt][nh * 4 + nt], af[0][mt], bl[nt]);
#pragma unroll
                for (int mt = 0; mt < 2; ++mt)
#pragma unroll
                    for (int nt = 0; nt < 4; ++nt)
                        mma16816(acc[mt][nh * 4 + nt], af[1][mt], bh[nt]);
            }
        }
        __syncthreads();
    }

    // epilogue
#pragma unroll
    for (int mt = 0; mt < 2; ++mt)
#pragma unroll
        for (int half = 0; half < 2; ++half) {
            const int m = m0 + wm * 32 + mt * 16 + g + half * 8;
            if (m >= M) continue;
#pragma unroll
            for (int ntg = 0; ntg < 8; ++ntg) {
                const int n = n0 + wn * 64 + ntg * 8 + 2 * c4;
                if (n >= N) continue;
                float2 o;
                o.x = acc[mt][ntg][half * 2 + 0] * alpha;
                o.y = acc[mt][ntg][half * 2 + 1] * alpha;
                if (bias) { o.x += bias[n]; o.y += bias[n + 1]; }
                const long off = (long)m * N + n;
                if (accum) {
                    float2 old = *(const float2*)(C + off);
                    o.x += old.x; o.y += old.y;
                }
                *(float2*)(C + off) = o;
                if (Chi) {
                    uint32_t h, l;
                    pack_split(o.x, o.y, h, l);
                    const int jj = n >> 1, jl = jj & 7;
                    const long so = (long)m * (N >> 1) + (jj & ~7) + KPERM(jl);
                    Chi[so] = h; Clo[so] = l;
                }
            }
        }
}

// ---------------------------------------------------------------------------
// transpose_split2: fp32 h[b][l][d] -> split h^T planes written into TWO
// combined B buffers (row stride st*, column offset of*, u32 units).
// ---------------------------------------------------------------------------
__global__ __launch_bounds__(256) void transpose_split2(
    const float* __restrict__ in,
    uint32_t* __restrict__ o1h, uint32_t* __restrict__ o1l, int st1, int of1,
    uint32_t* __restrict__ o2h, uint32_t* __restrict__ o2l, int st2, int of2,
    int L)
{
    __shared__ float t[32][33];
    const int b = blockIdx.z;
    const int l0 = blockIdx.x * 32;
    const int d0 = blockIdx.y * 32;
    in += (long)b * L * DM;
    const int tx = threadIdx.x & 31;
    const int ty = threadIdx.x >> 5;
#pragma unroll
    for (int i = ty; i < 32; i += 8)
        t[i][tx] = in[(long)(l0 + i) * DM + d0 + tx];
    __syncthreads();
#pragma unroll
    for (int q = 0; q < 2; ++q) {
        const int u = q * 256 + threadIdx.x;
        const int dl = u >> 4, pr = u & 15;
        float v0 = t[2 * pr][dl], v1 = t[2 * pr + 1][dl];
        uint32_t h, l;
        pack_split(v0, v1, h, l);
        const int jj = (l0 >> 1) + pr, jl = jj & 7;
        const int kk = (jj & ~7) + KPERM(jl);
        const long r1 = ((long)b * DM + d0 + dl) * st1 + of1 + kk;
        o1h[r1] = h; o1l[r1] = l;
        const long r2 = ((long)b * DM + d0 + dl) * st2 + of2 + kk;
        o2h[r2] = h; o2l[r2] = l;
    }
}

// ---------------------------------------------------------------------------
// Row softmax (p12): reads fp32 S, writes split P12 into combined buffer
// (row stride ost, column offset ooff, u32 units). S untouched.
// ---------------------------------------------------------------------------
template <int L2>
__global__ __launch_bounds__(256) void softmax12(
    const float* __restrict__ S, const float* __restrict__ mk,
    uint32_t* __restrict__ Phi, uint32_t* __restrict__ Plo,
    int L1, int c1, int c2, int ost, int ooff)
{
    constexpr int NU = L2 / 64;
    const int warp = threadIdx.x >> 5;
    const int lane = threadIdx.x & 31;
    const int b = blockIdx.y;
    const int i = blockIdx.x * 8 + warp;
    if (i >= L1) return;
    const float* row = S + ((long)b * L1 + i) * L2;
    const float* m2 = mk + (long)b * L2;

    float v[2 * NU];
    float mx = -INFINITY;
#pragma unroll
    for (int t = 0; t < NU; ++t) {
        const int jj = t * 32 + lane;
        const int j = 2 * jj;
        float2 sv = *(const float2*)(row + j);
        float2 mm = *(const float2*)(m2 + j);
        float al0 = ((j < c2) || (i >= c1 && (i - c1) >= (j - c2))) ? 1.f : 0.f;
        float al1 = ((j + 1 < c2) || (i >= c1 && (i - c1) >= (j + 1 - c2))) ? 1.f : 0.f;
        v[2 * t + 0] = sv.x + (1.f - al0 * mm.x) * -10000.f;
        v[2 * t + 1] = sv.y + (1.f - al1 * mm.y) * -10000.f;
        mx = fmaxf(mx, fmaxf(v[2 * t], v[2 * t + 1]));
    }
#pragma unroll
    for (int off = 16; off > 0; off >>= 1)
        mx = fmaxf(mx, __shfl_xor_sync(0xffffffffu, mx, off));
    float Z = 0.f;
#pragma unroll
    for (int t = 0; t < 2 * NU; ++t) { v[t] = __expf(v[t] - mx); Z += v[t]; }
#pragma unroll
    for (int off = 16; off > 0; off >>= 1)
        Z += __shfl_xor_sync(0xffffffffu, Z, off);
    const float inv = 1.f / Z;
    const long base = ((long)b * L1 + i) * ost + ooff;
#pragma unroll
    for (int t = 0; t < NU; ++t) {
        const int jj = t * 32 + lane, jl = jj & 7;
        uint32_t h, l;
        pack_split(v[2 * t] * inv, v[2 * t + 1] * inv, h, l);
        const long so = base + (jj & ~7) + KPERM(jl);
        Phi[so] = h; Plo[so] = l;
    }
}

// ---------------------------------------------------------------------------
// Column softmax (p21): P21[b,j,i] = softmax_i(S[b,i,j] + bias21), written as
// split planes (rows j, k = i) into combined buffer (stride ost, offset ooff).
// ---------------------------------------------------------------------------
__global__ __launch_bounds__(256) void softmax21(
    const float* __restrict__ S, const float* __restrict__ mk1,
    uint32_t* __restrict__ Phi, uint32_t* __restrict__ Plo,
    int L1, int L2, int c1, int c2, int ost, int ooff)
{
    const int tx = threadIdx.x & 31;
    const int ty = threadIdx.x >> 5;
    const int b = blockIdx.y;
    const int j0 = blockIdx.x * 32;
    const int j = j0 + tx;
    const float* Sb = S + (long)b * L1 * L2;
    const float* m1 = mk1 + (long)b * L1;

    float mx = -INFINITY, Z = 0.f;
    for (int i = ty; i < L1; i += 8) {
        float allowed = ((i < c1) || (j >= c2 && (j - c2) >= (i - c1))) ? 1.f : 0.f;
        float s = Sb[(long)i * L2 + j] + (1.f - allowed * m1[i]) * -10000.f;
        if (s > mx) { Z = Z * __expf(mx - s) + 1.f; mx = s; }
        else        { Z += __expf(s - mx); }
    }
    __shared__ float smx[8][32];
    __shared__ float ssum[8][32];
    smx[ty][tx] = mx; ssum[ty][tx] = Z;
    __syncthreads();
    if (ty == 0) {
        float m = smx[0][tx], z = ssum[0][tx];
#pragma unroll
        for (int r = 1; r < 8; ++r) {
            float m2 = smx[r][tx], z2 = ssum[r][tx];
            float mm = fmaxf(m, m2);
            z = z * __expf(m - mm) + z2 * __expf(m2 - mm);
            m = mm;
        }
        smx[0][tx] = m; ssum[0][tx] = 1.f / z;
    }
    __syncthreads();
    const float rowmax = smx[0][tx];
    const float invZ = ssum[0][tx];

    __shared__ float tile[32][33];
    for (int i0 = 0; i0 < L1; i0 += 32) {
#pragma unroll
        for (int ii = ty; ii < 32; ii += 8) {
            const int i = i0 + ii;
            float allowed = ((i < c1) || (j >= c2 && (j - c2) >= (i - c1))) ? 1.f : 0.f;
            float s = Sb[(long)i * L2 + j] + (1.f - allowed * m1[i]) * -10000.f;
            tile[tx][ii] = __expf(s - rowmax) * invZ;
        }
        __syncthreads();
#pragma unroll
        for (int q = 0; q < 2; ++q) {
            const int u = q * 256 + threadIdx.x;
            const int jl2 = u >> 4, pr = u & 15;
            uint32_t h, l;
            pack_split(tile[jl2][2 * pr], tile[jl2][2 * pr + 1], h, l);
            const int jj = (i0 >> 1) + pr, jg = jj & 7;
            const long so = ((long)b * L2 + j0 + jl2) * ost + ooff + (jj & ~7) + KPERM(jg);
            Phi[so] = h; Plo[so] = l;
        }
        __syncthreads();
    }
}

// ---------------------------------------------------------------------------
static inline dim3 gg(int M, int N, int batch) {
    return dim3((unsigned)((N + BN - 1) / BN), (unsigned)((M + BM - 1) / BM), (unsigned)batch);
}

extern "C" void kernel_launch(void* const* d_in, const int* in_sizes, int n_in,
                              void* d_out, int out_size)
{
    const float* vemb = (const float*)d_in[0];
    const float* mv   = (const float*)d_in[1];
    const float* demb = (const float*)d_in[2];
    const float* md   = (const float*)d_in[3];
    const float* aemb = (const float*)d_in[4];
    const float* ma   = (const float*)d_in[5];
    const float* Wv   = (const float*)d_in[6];
    const float* bv   = (const float*)d_in[7];
    const float* Wd   = (const float*)d_in[8];
    const float* bd   = (const float*)d_in[9];
    const float* Wa   = (const float*)d_in[10];
    const float* ba   = (const float*)d_in[11];

    float* out1 = (float*)d_out;
    float* out2 = out1 + (size_t)NB * LV * DM;
    float* out3 = out2 + (size_t)NB * LD * DM;

#define GA(v, s) cudaGetSymbolAddress((void**)&v, s)
    float *vid, *det, *act, *SA, *SB, *SC;
    uint32_t *xvh, *xvl, *xdh, *xdl, *xah, *xal;
    uint32_t *wvh, *wvl, *wdh, *wdl, *wah, *wal;
    uint32_t *vh, *vl, *dh, *dl, *ah, *al;
    uint32_t *B1h, *B1l, *B2h, *B2l, *B3h, *B3l;
    uint32_t *P1h, *P1l, *P2h, *P2l, *P3h, *P3l;
    GA(vid, g_vid); GA(det, g_det); GA(act, g_act);
    GA(SA, g_SA); GA(SB, g_SB); GA(SC, g_SC);
    GA(xvh, g_xvh); GA(xvl, g_xvl); GA(xdh, g_xdh); GA(xdl, g_xdl);
    GA(xah, g_xah); GA(xal, g_xal);
    GA(wvh, g_wvh); GA(wvl, g_wvl); GA(wdh, g_wdh); GA(wdl, g_wdl);
    GA(wah, g_wah); GA(wal, g_wal);
    GA(vh, g_vh); GA(vl, g_vl); GA(dh, g_dh); GA(dl, g_dl);
    GA(ah, g_ah); GA(al, g_al);
    GA(B1h, g_B1h); GA(B1l, g_B1l); GA(B2h, g_B2h); GA(B2l, g_B2l);
    GA(B3h, g_B3h); GA(B3l, g_B3l);
    GA(P1h, g_P1h); GA(P1l, g_P1l); GA(P2h, g_P2h); GA(P2l, g_P2l);
    GA(P3h, g_P3h); GA(P3l, g_P3l);
#undef GA

    cudaFuncSetAttribute(gemm_split, cudaFuncAttributeMaxDynamicSharedMemorySize, GEMM_SMEM);

    // ---- one-time host resources (no device allocation) ----
    static cudaStream_t s1 = nullptr, s2 = nullptr;
    static cudaEvent_t evFork, evD, evA2, evJoin, ev21A, ev12B, ev12C, evS1, evS2;
    if (!s1) {
        cudaStreamCreateWithFlags(&s1, cudaStreamNonBlocking);
        cudaStreamCreateWithFlags(&s2, cudaStreamNonBlocking);
        cudaEventCreateWithFlags(&evFork, cudaEventDisableTiming);
        cudaEventCreateWithFlags(&evD,    cudaEventDisableTiming);
        cudaEventCreateWithFlags(&evA2,   cudaEventDisableTiming);
        cudaEventCreateWithFlags(&evJoin, cudaEventDisableTiming);
        cudaEventCreateWithFlags(&ev21A,  cudaEventDisableTiming);
        cudaEventCreateWithFlags(&ev12B,  cudaEventDisableTiming);
        cudaEventCreateWithFlags(&ev12C,  cudaEventDisableTiming);
        cudaEventCreateWithFlags(&evS1,   cudaEventDisableTiming);
        cudaEventCreateWithFlags(&evS2,   cudaEventDisableTiming);
    }

    const long tv = (long)NB * LV * (DM / 16), td = (long)NB * LD * (DM / 16),
               ta = (long)NB * LA * (DM / 16), tw = (long)DM * (DM / 16);

    // ===== phase 0: fork the three projection chains =====
    cudaEventRecord(evFork, 0);
    cudaStreamWaitEvent(s1, evFork, 0);
    cudaStreamWaitEvent(s2, evFork, 0);

    // default: vid chain; vT -> B2 (off 0) and B3 (off 0)
    split_src<<<(unsigned)((tw + 255) / 256), 256>>>(Wv, wvh, wvl, tw, DM);
    split_src<<<(unsigned)((tv + 255) / 256), 256>>>(vemb, xvh, xvl, tv, DM);
    gemm_split<<<gg(NB * LV, DM, 1), 256, GEMM_SMEM>>>(xvh, xvl, wvh, wvl, bv, vid,
        vh, vl, NB * LV, DM, DM, 0, 0, 0, 1.f, 0);
    transpose_split2<<<dim3(LV / 32, DM / 32, NB), 256>>>(vid,
        B2h, B2l, S2, 0, B3h, B3l, S3, 0, LV);

    // s1: det chain; dT -> B1 (off 0) and B3 (off 288)
    split_src<<<(unsigned)((tw + 255) / 256), 256, 0, s1>>>(Wd, wdh, wdl, tw, DM);
    split_src<<<(unsigned)((td + 255) / 256), 256, 0, s1>>>(demb, xdh, xdl, td, DM);
    gemm_split<<<gg(NB * LD, DM, 1), 256, GEMM_SMEM, s1>>>(xdh, xdl, wdh, wdl, bd, det,
        dh, dl, NB * LD, DM, DM, 0, 0, 0, 1.f, 0);
    transpose_split2<<<dim3(LD / 32, DM / 32, NB), 256, 0, s1>>>(det,
        B1h, B1l, S1, 0, B3h, B3l, S3, OFF_288, LD);
    cudaEventRecord(evD, s1);

    // s2: act chain; aT -> B1 (off 160) and B2 (off 288)
    split_src<<<(unsigned)((tw + 255) / 256), 256, 0, s2>>>(Wa, wah, wal, tw, DM);
    split_src<<<(unsigned)((ta + 255) / 256), 256, 0, s2>>>(aemb, xah, xal, ta, DM);
    gemm_split<<<gg(NB * LA, DM, 1), 256, GEMM_SMEM, s2>>>(xah, xal, wah, wal, ba, act,
        ah, al, NB * LA, DM, DM, 0, 0, 0, 1.f, 0);
    transpose_split2<<<dim3(LA / 32, DM / 32, NB), 256, 0, s2>>>(act,
        B1h, B1l, S1, OFF_B1_ACT, B2h, B2l, S2, OFF_288, LA);
    cudaEventRecord(evA2, s2);

    // join (scores each need two modalities), then re-fork
    cudaStreamWaitEvent(0, evD, 0);
    cudaStreamWaitEvent(0, evA2, 0);
    cudaEventRecord(evJoin, 0);
    cudaStreamWaitEvent(s1, evJoin, 0);
    cudaStreamWaitEvent(s2, evJoin, 0);

    // ===== pair A (default): vid x det =====
    gemm_split<<<gg(LV, LD, NB), 256, GEMM_SMEM>>>(vh, vl, dh, dl, nullptr, SA,
        nullptr, nullptr, LV, LD, DM,
        (long)LV * (DM / 2), (long)LD * (DM / 2), (long)LV * LD, 0.125f, 0);
    softmax21<<<dim3(LD / 32, NB), 256>>>(SA, mv, P2h, P2l, LV, LD, CV, CD, S2, 0);
    cudaEventRecord(ev21A, 0);
    softmax12<LD><<<dim3(LV / 8, NB), 256>>>(SA, md, P1h, P1l, LV, CV, CD, S1, 0);

    // ===== pair B (s1): vid x act =====
    gemm_split<<<gg(LV, LA, NB), 256, GEMM_SMEM, s1>>>(vh, vl, ah, al, nullptr, SB,
        nullptr, nullptr, LV, LA, DM,
        (long)LV * (DM / 2), (long)LA * (DM / 2), (long)LV * LA, 0.125f, 0);
    softmax12<LA><<<dim3(LV / 8, NB), 256, 0, s1>>>(SB, ma, P1h, P1l, LV, CV, CA, S1, OFF_B1_ACT);
    cudaEventRecord(ev12B, s1);
    softmax21<<<dim3(LA / 32, NB), 256, 0, s1>>>(SB, mv, P3h, P3l, LV, LA, CV, CA, S3, 0);

    // ===== pair C (s2): act x det =====
    gemm_split<<<gg(LA, LD, NB), 256, GEMM_SMEM, s2>>>(ah, al, dh, dl, nullptr, SC,
        nullptr, nullptr, LA, LD, DM,
        (long)LA * (DM / 2), (long)LD * (DM / 2), (long)LA * LD, 0.125f, 0);
    softmax12<LD><<<dim3(LA / 8, NB), 256, 0, s2>>>(SC, md, P3h, P3l, LA, CA, CD, S3, OFF_288);
    cudaEventRecord(ev12C, s2);
    softmax21<<<dim3(LD / 32, NB), 256, 0, s2>>>(SC, ma, P2h, P2l, LA, LD, CA, CD, S2, OFF_288);

    // ===== fused output GEMMs =====
    // out1 (default): [p12A | p12B] @ B1, K=512
    cudaStreamWaitEvent(0, ev12B, 0);
    gemm_split<<<gg(LV, DM, NB), 256, GEMM_SMEM>>>(P1h, P1l, B1h, B1l, nullptr, out1,
        nullptr, nullptr, LV, DM, K1,
        (long)LV * S1, (long)DM * S1, (long)LV * DM, 1.f, 0);
    // out3 (s1): [p21B | p12C] @ B3, K=896
    cudaStreamWaitEvent(s1, ev12C, 0);
    gemm_split<<<gg(LA, DM, NB), 256, GEMM_SMEM, s1>>>(P3h, P3l, B3h, B3l, nullptr, out3,
        nullptr, nullptr, LA, DM, K3,
        (long)LA * S3, (long)DM * S3, (long)LA * DM, 1.f, 0);
    cudaEventRecord(evS1, s1);
    // out2 (s2): [p21A | p21C] @ B2, K=768
    cudaStreamWaitEvent(s2, ev21A, 0);
    gemm_split<<<gg(LD, DM, NB), 256, GEMM_SMEM, s2>>>(P2h, P2l, B2h, B2l, nullptr, out2,
        nullptr, nullptr, LD, DM, K2C,
        (long)LD * S2, (long)DM * S2, (long)LD * DM, 1.f, 0);
    cudaEventRecord(evS2, s2);

    // final join onto default stream
    cudaStreamWaitEvent(0, evS1, 0);
    cudaStreamWaitEvent(0, evS2, 0);
}

// round 16
// speedup vs baseline: 1.4408x; 1.0599x over previous
#include <cuda_runtime.h>
#include <cuda_bf16.h>
#include <cstdint>
#include <math.h>

#define NB 64
#define DM 768
#define LV 576
#define LD 320
#define LA 192
#define CV 512
#define CD 256
#define CA 128

// GEMM tile config (R8 proven config)
#define BM 128
#define BN 128
#define AST 24                   // conflict-free fragment loads
#define PL  (128 * AST)
#define BUF (4 * PL)
#define GEMM_SMEM (2 * BUF * 4)  // 98304 B

#define KPERM(jl) ((((jl) & 3) * 2) + ((jl) >> 2))

// combined-K layout (u32 units per row)
#define K1 512                   // out1: [p12A(320) | p12B(192)]
#define K2C 768                  // out2: [p21A(576) | p21C(192)]
#define K3 896                   // out3: [p21B(576) | p12C(320)]
#define S1 (K1 / 2)
#define S2 (K2C / 2)
#define S3 (K3 / 2)
#define OFF_B1_ACT 160
#define OFF_288 288

// ---------------- scratch (device globals; no runtime allocation) ----------
__device__ float g_vid[(size_t)NB * LV * DM];
__device__ float g_det[(size_t)NB * LD * DM];
__device__ float g_act[(size_t)NB * LA * DM];
__device__ uint32_t g_xvh[(size_t)NB * LV * (DM / 2)], g_xvl[(size_t)NB * LV * (DM / 2)];
__device__ uint32_t g_xdh[(size_t)NB * LD * (DM / 2)], g_xdl[(size_t)NB * LD * (DM / 2)];
__device__ uint32_t g_xah[(size_t)NB * LA * (DM / 2)], g_xal[(size_t)NB * LA * (DM / 2)];
__device__ uint32_t g_wvh[DM * (DM / 2)], g_wvl[DM * (DM / 2)];
__device__ uint32_t g_wdh[DM * (DM / 2)], g_wdl[DM * (DM / 2)];
__device__ uint32_t g_wah[DM * (DM / 2)], g_wal[DM * (DM / 2)];
__device__ uint32_t g_vh[(size_t)NB * LV * (DM / 2)], g_vl[(size_t)NB * LV * (DM / 2)];
__device__ uint32_t g_dh[(size_t)NB * LD * (DM / 2)], g_dl[(size_t)NB * LD * (DM / 2)];
__device__ uint32_t g_ah[(size_t)NB * LA * (DM / 2)], g_al[(size_t)NB * LA * (DM / 2)];
__device__ uint32_t g_B1h[(size_t)NB * DM * S1], g_B1l[(size_t)NB * DM * S1];
__device__ uint32_t g_B2h[(size_t)NB * DM * S2], g_B2l[(size_t)NB * DM * S2];
__device__ uint32_t g_B3h[(size_t)NB * DM * S3], g_B3l[(size_t)NB * DM * S3];
__device__ float g_SA[(size_t)NB * LV * LD];
__device__ float g_SB[(size_t)NB * LV * LA];
__device__ float g_SC[(size_t)NB * LA * LD];
__device__ uint32_t g_P1h[(size_t)NB * LV * S1], g_P1l[(size_t)NB * LV * S1];
__device__ uint32_t g_P2h[(size_t)NB * LD * S2], g_P2l[(size_t)NB * LD * S2];
__device__ uint32_t g_P3h[(size_t)NB * LA * S3], g_P3l[(size_t)NB * LA * S3];

// ---------------- helpers ---------------------------------------------------
__device__ __forceinline__ uint32_t smem_u32(const void* p) {
    uint32_t a;
    asm("{ .reg .u64 t; cvta.to.shared.u64 t, %1; cvt.u32.u64 %0, t; }" : "=r"(a) : "l"(p));
    return a;
}

__device__ __forceinline__ void mma16816(float* d, const uint32_t* a, const uint32_t* b)
{
    asm volatile(
        "mma.sync.aligned.m16n8k16.row.col.f32.bf16.bf16.f32 "
        "{%0,%1,%2,%3}, {%4,%5,%6,%7}, {%8,%9}, {%0,%1,%2,%3};"
        : "+f"(d[0]), "+f"(d[1]), "+f"(d[2]), "+f"(d[3])
        : "r"(a[0]), "r"(a[1]), "r"(a[2]), "r"(a[3]), "r"(b[0]), "r"(b[1]));
}

__device__ __forceinline__ void pack_split(float x, float y, uint32_t& hi, uint32_t& lo)
{
    __nv_bfloat162 h = __floats2bfloat162_rn(x, y);
    float hx = __bfloat162float(__low2bfloat16(h));
    float hy = __bfloat162float(__high2bfloat16(h));
    __nv_bfloat162 l = __floats2bfloat162_rn(x - hx, y - hy);
    hi = *reinterpret_cast<uint32_t*>(&h);
    lo = *reinterpret_cast<uint32_t*>(&l);
}

// ---------------------------------------------------------------------------
// split_src: fp32 row-major [rows, Kf] -> hi/lo bf16x2 planes, pre-permuted.
// ---------------------------------------------------------------------------
__global__ __launch_bounds__(256) void split_src(
    const float* __restrict__ in, uint32_t* __restrict__ hi, uint32_t* __restrict__ lo,
    long total, int Kf)
{
    long u = (long)blockIdx.x * 256 + threadIdx.x;
    if (u >= total) return;
    const int gpr = Kf >> 4;
    long row = u / gpr;
    int grp = (int)(u - row * gpr);
    const float* p = in + row * (long)Kf + grp * 16;
    float f[16];
#pragma unroll
    for (int q = 0; q < 4; ++q) *(float4*)(f + q * 4) = *(const float4*)(p + q * 4);
    uint32_t h[8], l[8];
#pragma unroll
    for (int j = 0; j < 8; ++j) pack_split(f[2 * j], f[2 * j + 1], h[j], l[j]);
    uint32_t* dh = hi + row * (long)(Kf >> 1) + grp * 8;
    uint32_t* dl = lo + row * (long)(Kf >> 1) + grp * 8;
    *(uint4*)(dh + 0) = make_uint4(h[0], h[4], h[1], h[5]);
    *(uint4*)(dh + 4) = make_uint4(h[2], h[6], h[3], h[7]);
    *(uint4*)(dl + 0) = make_uint4(l[0], l[4], l[1], l[5]);
    *(uint4*)(dl + 4) = make_uint4(l[2], l[6], l[3], l[7]);
}

// ---------------------------------------------------------------------------
// gemm_split: NT GEMM on pre-split pre-permuted bf16 planes.
// cthr_r/cmask: if m0+BM<=cthr_r, skip K-chunks whose bit is set in cmask
//   (those P columns are exactly zero — fp32 softmax underflow).
// NOTE: no score-tile early-return — S is consumed by BOTH softmax masks and
// their allowed-regions cover the full matrix (R13 post-mortem).
// ---------------------------------------------------------------------------
__global__ __launch_bounds__(256, 2) void gemm_split(
    const uint32_t* __restrict__ Ah, const uint32_t* __restrict__ Al,
    const uint32_t* __restrict__ Bh, const uint32_t* __restrict__ Bl,
    const float* __restrict__ bias, float* __restrict__ C,
    uint32_t* __restrict__ Chi, uint32_t* __restrict__ Clo,
    int M, int N, int K, long sA, long sB, long sC, float alpha, int accum,
    int cthr_r, uint32_t cmask_in)
{
    extern __shared__ uint32_t sm[];
    const int tid = threadIdx.x;
    const int bz = blockIdx.z;
    const int m0 = blockIdx.y * BM;
    const int n0 = blockIdx.x * BN;

    Ah += (long)bz * sA; Al += (long)bz * sA;
    Bh += (long)bz * sB; Bl += (long)bz * sB;
    C  += (long)bz * sC;

    const int K2 = K >> 1;
    const int nc = K >> 5;
    const uint32_t cmask = (cthr_r >= 0 && m0 + BM <= cthr_r) ? cmask_in : 0u;

    const int wid = tid >> 5, lane = tid & 31;
    const int wm = wid >> 1, wn = wid & 1;
    const int g = lane >> 2, c4 = lane & 3;

    const uint32_t smem_base = smem_u32(sm);

    float acc[2][8][4];
#pragma unroll
    for (int mt = 0; mt < 2; ++mt)
#pragma unroll
        for (int nt = 0; nt < 8; ++nt)
#pragma unroll
            for (int q = 0; q < 4; ++q) acc[mt][nt][q] = 0.f;

    auto issue = [&](int cc, int buf) {
#pragma unroll
        for (int it = 0; it < 8; ++it) {
            const int plane = it >> 1;
            const int u = ((it & 1) << 8) + tid;
            const int row = u >> 2, ch = u & 3;
            uint32_t dst = smem_base +
                (uint32_t)((buf * BUF + plane * PL + row * AST + ch * 4) * 4);
            const uint32_t* srcb;
            bool valid;
            if (plane < 2) {
                valid = (m0 + row) < M;
                srcb = (plane == 0 ? Ah : Al) + (long)(valid ? m0 + row : 0) * K2 + cc * 16 + ch * 4;
            } else {
                valid = (n0 + row) < N;
                srcb = (plane == 2 ? Bh : Bl) + (long)(valid ? n0 + row : 0) * K2 + cc * 16 + ch * 4;
            }
            int sb = valid ? 16 : 0;
            asm volatile("cp.async.cg.shared.global [%0], [%1], 16, %2;"
                         :: "r"(dst), "l"(srcb), "r"(sb) : "memory");
        }
        asm volatile("cp.async.commit_group;" ::: "memory");
    };

    auto nxtact = [&](int c) {
        while (c < nc && ((cmask >> c) & 1u)) ++c;
        return c;
    };

    int cur = nxtact(0);
    int buf = 0;
    issue(cur, buf);

    while (true) {
        const int nx = nxtact(cur + 1);
        if (nx < nc) {
            issue(nx, buf ^ 1);
            asm volatile("cp.async.wait_group 1;" ::: "memory");
        } else {
            asm volatile("cp.async.wait_group 0;" ::: "memory");
        }
        __syncthreads();

        const uint32_t* Pa_h = sm + buf * BUF;
        const uint32_t* Pa_l = Pa_h + PL;
        const uint32_t* Pb_h = Pa_h + 2 * PL;
        const uint32_t* Pb_l = Pa_h + 3 * PL;

#pragma unroll
        for (int s = 0; s < 2; ++s) {
            const int kc = s * 8 + 2 * c4;
            uint32_t af[2][2][4];
#pragma unroll
            for (int mt = 0; mt < 2; ++mt) {
                const int r = wm * 32 + mt * 16 + g;
                uint2 t0 = *(const uint2*)(Pa_h + r * AST + kc);
                uint2 t1 = *(const uint2*)(Pa_h + (r + 8) * AST + kc);
                af[0][mt][0] = t0.x; af[0][mt][1] = t1.x;
                af[0][mt][2] = t0.y; af[0][mt][3] = t1.y;
                t0 = *(const uint2*)(Pa_l + r * AST + kc);
                t1 = *(const uint2*)(Pa_l + (r + 8) * AST + kc);
                af[1][mt][0] = t0.x; af[1][mt][1] = t1.x;
                af[1][mt][2] = t0.y; af[1][mt][3] = t1.y;
            }
#pragma unroll
            for (int nh = 0; nh < 2; ++nh) {
                uint32_t bh[4][2], bl[4][2];
#pragma unroll
                for (int nt = 0; nt < 4; ++nt) {
                    const int rb = wn * 64 + nh * 32 + nt * 8 + g;
                    uint2 t = *(const uint2*)(Pb_h + rb * AST + kc);
                    bh[nt][0] = t.x; bh[nt][1] = t.y;
                    t = *(const uint2*)(Pb_l + rb * AST + kc);
                    bl[nt][0] = t.x; bl[nt][1] = t.y;
                }
#pragma unroll
                for (int mt = 0; mt < 2; ++mt)
#pragma unroll
                    for (int nt = 0; nt < 4; ++nt)
                        mma16816(acc[mt][nh * 4 + nt], af[0][mt], bh[nt]);
#pragma unroll
                for (int mt = 0; mt < 2; ++mt)
#pragma unroll
                    for (int nt = 0; nt < 4; ++nt)
                        mma16816(acc[mt][nh * 4 + nt], af[0][mt], bl[nt]);
#pragma unroll
                for (int mt = 0; mt < 2; ++mt)
#pragma unroll
                    for (int nt = 0; nt < 4; ++nt)
                        mma16816(acc[mt][nh * 4 + nt], af[1][mt], bh[nt]);
            }
        }
        __syncthreads();
        if (nx >= nc) break;
        cur = nx;
        buf ^= 1;
    }

    // epilogue
#pragma unroll
    for (int mt = 0; mt < 2; ++mt)
#pragma unroll
        for (int half = 0; half < 2; ++half) {
            const int m = m0 + wm * 32 + mt * 16 + g + half * 8;
            if (m >= M) continue;
#pragma unroll
            for (int ntg = 0; ntg < 8; ++ntg) {
                const int n = n0 + wn * 64 + ntg * 8 + 2 * c4;
                if (n >= N) continue;
                float2 o;
                o.x = acc[mt][ntg][half * 2 + 0] * alpha;
                o.y = acc[mt][ntg][half * 2 + 1] * alpha;
                if (bias) { o.x += bias[n]; o.y += bias[n + 1]; }
                const long off = (long)m * N + n;
                if (accum) {
                    float2 old = *(const float2*)(C + off);
                    o.x += old.x; o.y += old.y;
                }
                *(float2*)(C + off) = o;
                if (Chi) {
                    uint32_t h, l;
                    pack_split(o.x, o.y, h, l);
                    const int jj = n >> 1, jl = jj & 7;
                    const long so = (long)m * (N >> 1) + (jj & ~7) + KPERM(jl);
                    Chi[so] = h; Clo[so] = l;
                }
            }
        }
}

// ---------------------------------------------------------------------------
// transpose_split2: fp32 h[b][l][d] -> split h^T planes into TWO combined
// B buffers (row stride st*, column offset of*, u32 units).
// ---------------------------------------------------------------------------
__global__ __launch_bounds__(256) void transpose_split2(
    const float* __restrict__ in,
    uint32_t* __restrict__ o1h, uint32_t* __restrict__ o1l, int st1, int of1,
    uint32_t* __restrict__ o2h, uint32_t* __restrict__ o2l, int st2, int of2,
    int L)
{
    __shared__ float t[32][33];
    const int b = blockIdx.z;
    const int l0 = blockIdx.x * 32;
    const int d0 = blockIdx.y * 32;
    in += (long)b * L * DM;
    const int tx = threadIdx.x & 31;
    const int ty = threadIdx.x >> 5;
#pragma unroll
    for (int i = ty; i < 32; i += 8)
        t[i][tx] = in[(long)(l0 + i) * DM + d0 + tx];
    __syncthreads();
#pragma unroll
    for (int q = 0; q < 2; ++q) {
        const int u = q * 256 + threadIdx.x;
        const int dl = u >> 4, pr = u & 15;
        float v0 = t[2 * pr][dl], v1 = t[2 * pr + 1][dl];
        uint32_t h, l;
        pack_split(v0, v1, h, l);
        const int jj = (l0 >> 1) + pr, jl = jj & 7;
        const int kk = (jj & ~7) + KPERM(jl);
        const long r1 = ((long)b * DM + d0 + dl) * st1 + of1 + kk;
        o1h[r1] = h; o1l[r1] = l;
        const long r2 = ((long)b * DM + d0 + dl) * st2 + of2 + kk;
        o2h[r2] = h; o2l[r2] = l;
    }
}

// ---------------------------------------------------------------------------
// Row softmax (p12): writes split P12 into combined buffer (ost/ooff u32).
// ---------------------------------------------------------------------------
template <int L2>
__global__ __launch_bounds__(256) void softmax12(
    const float* __restrict__ S, const float* __restrict__ mk,
    uint32_t* __restrict__ Phi, uint32_t* __restrict__ Plo,
    int L1, int c1, int c2, int ost, int ooff)
{
    constexpr int NU = L2 / 64;
    const int warp = threadIdx.x >> 5;
    const int lane = threadIdx.x & 31;
    const int b = blockIdx.y;
    const int i = blockIdx.x * 8 + warp;
    if (i >= L1) return;
    const float* row = S + ((long)b * L1 + i) * L2;
    const float* m2 = mk + (long)b * L2;

    float v[2 * NU];
    float mx = -INFINITY;
#pragma unroll
    for (int t = 0; t < NU; ++t) {
        const int jj = t * 32 + lane;
        const int j = 2 * jj;
        float2 sv = *(const float2*)(row + j);
        float2 mm = *(const float2*)(m2 + j);
        float al0 = ((j < c2) || (i >= c1 && (i - c1) >= (j - c2))) ? 1.f : 0.f;
        float al1 = ((j + 1 < c2) || (i >= c1 && (i - c1) >= (j + 1 - c2))) ? 1.f : 0.f;
        v[2 * t + 0] = sv.x + (1.f - al0 * mm.x) * -10000.f;
        v[2 * t + 1] = sv.y + (1.f - al1 * mm.y) * -10000.f;
        mx = fmaxf(mx, fmaxf(v[2 * t], v[2 * t + 1]));
    }
#pragma unroll
    for (int off = 16; off > 0; off >>= 1)
        mx = fmaxf(mx, __shfl_xor_sync(0xffffffffu, mx, off));
    float Z = 0.f;
#pragma unroll
    for (int t = 0; t < 2 * NU; ++t) { v[t] = __expf(v[t] - mx); Z += v[t]; }
#pragma unroll
    for (int off = 16; off > 0; off >>= 1)
        Z += __shfl_xor_sync(0xffffffffu, Z, off);
    const float inv = 1.f / Z;
    const long base = ((long)b * L1 + i) * ost + ooff;
#pragma unroll
    for (int t = 0; t < NU; ++t) {
        const int jj = t * 32 + lane, jl = jj & 7;
        uint32_t h, l;
        pack_split(v[2 * t] * inv, v[2 * t + 1] * inv, h, l);
        const long so = base + (jj & ~7) + KPERM(jl);
        Phi[so] = h; Plo[so] = l;
    }
}

// ---------------------------------------------------------------------------
// Column softmax (p21): writes split P21 into combined buffer (ost/ooff u32).
// ---------------------------------------------------------------------------
__global__ __launch_bounds__(256) void softmax21(
    const float* __restrict__ S, const float* __restrict__ mk1,
    uint32_t* __restrict__ Phi, uint32_t* __restrict__ Plo,
    int L1, int L2, int c1, int c2, int ost, int ooff)
{
    const int tx = threadIdx.x & 31;
    const int ty = threadIdx.x >> 5;
    const int b = blockIdx.y;
    const int j0 = blockIdx.x * 32;
    const int j = j0 + tx;
    const float* Sb = S + (long)b * L1 * L2;
    const float* m1 = mk1 + (long)b * L1;

    float mx = -INFINITY, Z = 0.f;
    for (int i = ty; i < L1; i += 8) {
        float allowed = ((i < c1) || (j >= c2 && (j - c2) >= (i - c1))) ? 1.f : 0.f;
        float s = Sb[(long)i * L2 + j] + (1.f - allowed * m1[i]) * -10000.f;
        if (s > mx) { Z = Z * __expf(mx - s) + 1.f; mx = s; }
        else        { Z += __expf(s - mx); }
    }
    __shared__ float smx[8][32];
    __shared__ float ssum[8][32];
    smx[ty][tx] = mx; ssum[ty][tx] = Z;
    __syncthreads();
    if (ty == 0) {
        float m = smx[0][tx], z = ssum[0][tx];
#pragma unroll
        for (int r = 1; r < 8; ++r) {
            float m2 = smx[r][tx], z2 = ssum[r][tx];
            float mm = fmaxf(m, m2);
            z = z * __expf(m - mm) + z2 * __expf(m2 - mm);
            m = mm;
        }
        smx[0][tx] = m; ssum[0][tx] = 1.f / z;
    }
    __syncthreads();
    const float rowmax = smx[0][tx];
    const float invZ = ssum[0][tx];

    __shared__ float tile[32][33];
    for (int i0 = 0; i0 < L1; i0 += 32) {
#pragma unroll
        for (int ii = ty; ii < 32; ii += 8) {
            const int i = i0 + ii;
            float allowed = ((i < c1) || (j >= c2 && (j - c2) >= (i - c1))) ? 1.f : 0.f;
            float s = Sb[(long)i * L2 + j] + (1.f - allowed * m1[i]) * -10000.f;
            tile[tx][ii] = __expf(s - rowmax) * invZ;
        }
        __syncthreads();
#pragma unroll
        for (int q = 0; q < 2; ++q) {
            const int u = q * 256 + threadIdx.x;
            const int jl2 = u >> 4, pr = u & 15;
            uint32_t h, l;
            pack_split(tile[jl2][2 * pr], tile[jl2][2 * pr + 1], h, l);
            const int jj = (i0 >> 1) + pr, jg = jj & 7;
            const long so = ((long)b * L2 + j0 + jl2) * ost + ooff + (jj & ~7) + KPERM(jg);
            Phi[so] = h; Plo[so] = l;
        }
        __syncthreads();
    }
}

// ---------------------------------------------------------------------------
static inline dim3 gg(int M, int N, int batch) {
    return dim3((unsigned)((N + BN - 1) / BN), (unsigned)((M + BM - 1) / BM), (unsigned)batch);
}

extern "C" void kernel_launch(void* const* d_in, const int* in_sizes, int n_in,
                              void* d_out, int out_size)
{
    const float* vemb = (const float*)d_in[0];
    const float* mv   = (const float*)d_in[1];
    const float* demb = (const float*)d_in[2];
    const float* md   = (const float*)d_in[3];
    const float* aemb = (const float*)d_in[4];
    const float* ma   = (const float*)d_in[5];
    const float* Wv   = (const float*)d_in[6];
    const float* bv   = (const float*)d_in[7];
    const float* Wd   = (const float*)d_in[8];
    const float* bd   = (const float*)d_in[9];
    const float* Wa   = (const float*)d_in[10];
    const float* ba   = (const float*)d_in[11];

    float* out1 = (float*)d_out;
    float* out2 = out1 + (size_t)NB * LV * DM;
    float* out3 = out2 + (size_t)NB * LD * DM;

#define GA(v, s) cudaGetSymbolAddress((void**)&v, s)
    float *vid, *det, *act, *SA, *SB, *SC;
    uint32_t *xvh, *xvl, *xdh, *xdl, *xah, *xal;
    uint32_t *wvh, *wvl, *wdh, *wdl, *wah, *wal;
    uint32_t *vh, *vl, *dh, *dl, *ah, *al;
    uint32_t *B1h, *B1l, *B2h, *B2l, *B3h, *B3l;
    uint32_t *P1h, *P1l, *P2h, *P2l, *P3h, *P3l;
    GA(vid, g_vid); GA(det, g_det); GA(act, g_act);
    GA(SA, g_SA); GA(SB, g_SB); GA(SC, g_SC);
    GA(xvh, g_xvh); GA(xvl, g_xvl); GA(xdh, g_xdh); GA(xdl, g_xdl);
    GA(xah, g_xah); GA(xal, g_xal);
    GA(wvh, g_wvh); GA(wvl, g_wvl); GA(wdh, g_wdh); GA(wdl, g_wdl);
    GA(wah, g_wah); GA(wal, g_wal);
    GA(vh, g_vh); GA(vl, g_vl); GA(dh, g_dh); GA(dl, g_dl);
    GA(ah, g_ah); GA(al, g_al);
    GA(B1h, g_B1h); GA(B1l, g_B1l); GA(B2h, g_B2h); GA(B2l, g_B2l);
    GA(B3h, g_B3h); GA(B3l, g_B3l);
    GA(P1h, g_P1h); GA(P1l, g_P1l); GA(P2h, g_P2h); GA(P2l, g_P2l);
    GA(P3h, g_P3h); GA(P3l, g_P3l);
#undef GA

    cudaFuncSetAttribute(gemm_split, cudaFuncAttributeMaxDynamicSharedMemorySize, GEMM_SMEM);

    static cudaStream_t s1 = nullptr, s2 = nullptr;
    static cudaEvent_t evFork, evD, evA2, evJoin, ev21A, ev12B, ev12C, evS1, evS2;
    if (!s1) {
        cudaStreamCreateWithFlags(&s1, cudaStreamNonBlocking);
        cudaStreamCreateWithFlags(&s2, cudaStreamNonBlocking);
        cudaEventCreateWithFlags(&evFork, cudaEventDisableTiming);
        cudaEventCreateWithFlags(&evD,    cudaEventDisableTiming);
        cudaEventCreateWithFlags(&evA2,   cudaEventDisableTiming);
        cudaEventCreateWithFlags(&evJoin, cudaEventDisableTiming);
        cudaEventCreateWithFlags(&ev21A,  cudaEventDisableTiming);
        cudaEventCreateWithFlags(&ev12B,  cudaEventDisableTiming);
        cudaEventCreateWithFlags(&ev12C,  cudaEventDisableTiming);
        cudaEventCreateWithFlags(&evS1,   cudaEventDisableTiming);
        cudaEventCreateWithFlags(&evS2,   cudaEventDisableTiming);
    }

    const long tv = (long)NB * LV * (DM / 16), td = (long)NB * LD * (DM / 16),
               ta = (long)NB * LA * (DM / 16), tw = (long)DM * (DM / 16);

    // ===== phase 0: fork the three projection chains =====
    cudaEventRecord(evFork, 0);
    cudaStreamWaitEvent(s1, evFork, 0);
    cudaStreamWaitEvent(s2, evFork, 0);

    split_src<<<(unsigned)((tw + 255) / 256), 256>>>(Wv, wvh, wvl, tw, DM);
    split_src<<<(unsigned)((tv + 255) / 256), 256>>>(vemb, xvh, xvl, tv, DM);
    gemm_split<<<gg(NB * LV, DM, 1), 256, GEMM_SMEM>>>(xvh, xvl, wvh, wvl, bv, vid,
        vh, vl, NB * LV, DM, DM, 0, 0, 0, 1.f, 0, -1, 0u);
    transpose_split2<<<dim3(LV / 32, DM / 32, NB), 256>>>(vid,
        B2h, B2l, S2, 0, B3h, B3l, S3, 0, LV);

    split_src<<<(unsigned)((tw + 255) / 256), 256, 0, s1>>>(Wd, wdh, wdl, tw, DM);
    split_src<<<(unsigned)((td + 255) / 256), 256, 0, s1>>>(demb, xdh, xdl, td, DM);
    gemm_split<<<gg(NB * LD, DM, 1), 256, GEMM_SMEM, s1>>>(xdh, xdl, wdh, wdl, bd, det,
        dh, dl, NB * LD, DM, DM, 0, 0, 0, 1.f, 0, -1, 0u);
    transpose_split2<<<dim3(LD / 32, DM / 32, NB), 256, 0, s1>>>(det,
        B1h, B1l, S1, 0, B3h, B3l, S3, OFF_288, LD);
    cudaEventRecord(evD, s1);

    split_src<<<(unsigned)((tw + 255) / 256), 256, 0, s2>>>(Wa, wah, wal, tw, DM);
    split_src<<<(unsigned)((ta + 255) / 256), 256, 0, s2>>>(aemb, xah, xal, ta, DM);
    gemm_split<<<gg(NB * LA, DM, 1), 256, GEMM_SMEM, s2>>>(xah, xal, wah, wal, ba, act,
        ah, al, NB * LA, DM, DM, 0, 0, 0, 1.f, 0, -1, 0u);
    transpose_split2<<<dim3(LA / 32, DM / 32, NB), 256, 0, s2>>>(act,
        B1h, B1l, S1, OFF_B1_ACT, B2h, B2l, S2, OFF_288, LA);
    cudaEventRecord(evA2, s2);

    cudaStreamWaitEvent(0, evD, 0);
    cudaStreamWaitEvent(0, evA2, 0);
    cudaEventRecord(evJoin, 0);
    cudaStreamWaitEvent(s1, evJoin, 0);
    cudaStreamWaitEvent(s2, evJoin, 0);

    // ===== pair A (default): vid x det — FULL score GEMM =====
    gemm_split<<<gg(LV, LD, NB), 256, GEMM_SMEM>>>(vh, vl, dh, dl, nullptr, SA,
        nullptr, nullptr, LV, LD, DM,
        (long)LV * (DM / 2), (long)LD * (DM / 2), (long)LV * LD, 0.125f, 0, -1, 0u);
    softmax21<<<dim3(LD / 32, NB), 256>>>(SA, mv, P2h, P2l, LV, LD, CV, CD, S2, 0);
    cudaEventRecord(ev21A, 0);
    softmax12<LD><<<dim3(LV / 8, NB), 256>>>(SA, md, P1h, P1l, LV, CV, CD, S1, 0);

    // ===== pair B (s1): vid x act — FULL score GEMM =====
    gemm_split<<<gg(LV, LA, NB), 256, GEMM_SMEM, s1>>>(vh, vl, ah, al, nullptr, SB,
        nullptr, nullptr, LV, LA, DM,
        (long)LV * (DM / 2), (long)LA * (DM / 2), (long)LV * LA, 0.125f, 0, -1, 0u);
    softmax12<LA><<<dim3(LV / 8, NB), 256, 0, s1>>>(SB, ma, P1h, P1l, LV, CV, CA, S1, OFF_B1_ACT);
    cudaEventRecord(ev12B, s1);
    softmax21<<<dim3(LA / 32, NB), 256, 0, s1>>>(SB, mv, P3h, P3l, LV, LA, CV, CA, S3, 0);

    // ===== pair C (s2): act x det — FULL score GEMM =====
    gemm_split<<<gg(LA, LD, NB), 256, GEMM_SMEM, s2>>>(ah, al, dh, dl, nullptr, SC,
        nullptr, nullptr, LA, LD, DM,
        (long)LA * (DM / 2), (long)LD * (DM / 2), (long)LA * LD, 0.125f, 0, -1, 0u);
    softmax12<LD><<<dim3(LA / 8, NB), 256, 0, s2>>>(SC, md, P3h, P3l, LA, CA, CD, S3, OFF_288);
    cudaEventRecord(ev12C, s2);
    softmax21<<<dim3(LD / 32, NB), 256, 0, s2>>>(SC, ma, P2h, P2l, LA, LD, CA, CD, S2, OFF_288);

    // ===== fused output GEMMs with verified zero-chunk skipping =====
    // out1: K=512; m<512 tiles skip chunks {8,9,14,15}
    cudaStreamWaitEvent(0, ev12B, 0);
    gemm_split<<<gg(LV, DM, NB), 256, GEMM_SMEM>>>(P1h, P1l, B1h, B1l, nullptr, out1,
        nullptr, nullptr, LV, DM, K1,
        (long)LV * S1, (long)DM * S1, (long)LV * DM, 1.f, 0,
        CV, 0x0000C300u);
    // out3: K=896; m<128 tiles skip {16,17,26,27}
    cudaStreamWaitEvent(s1, ev12C, 0);
    gemm_split<<<gg(LA, DM, NB), 256, GEMM_SMEM, s1>>>(P3h, P3l, B3h, B3l, nullptr, out3,
        nullptr, nullptr, LA, DM, K3,
        (long)LA * S3, (long)DM * S3, (long)LA * DM, 1.f, 0,
        CA, 0x0C030000u);
    cudaEventRecord(evS1, s1);
    // out2: K=768; m<256 tiles skip {16,17,22,23}
    cudaStreamWaitEvent(s2, ev21A, 0);
    gemm_split<<<gg(LD, DM, NB), 256, GEMM_SMEM, s2>>>(P2h, P2l, B2h, B2l, nullptr, out2,
        nullptr, nullptr, LD, DM, K2C,
        (long)LD * S2, (long)DM * S2, (long)LD * DM, 1.f, 0,
        CD, 0x00C30000u);
    cudaEventRecord(evS2, s2);

    cudaStreamWaitEvent(0, evS1, 0);
    cudaStreamWaitEvent(0, evS2, 0);
}